// round 1
// baseline (speedup 1.0000x reference)
#include <cuda_runtime.h>
#include <math.h>

// Shapes (fixed for this problem)
#define BS   8
#define C    128
#define CH   64
#define NTOK 4096   // 64*64 tokens
#define TM   64     // query tile
#define TN   64     // key tile

// Scratch (static device memory — no allocation in kernel_launch)
__device__ float g_Q[BS * CH * NTOK];    // [b][d][n]  channel-major, relu(W_tgt.tgt)
__device__ float g_K[BS * CH * NTOK];    // [b][d][n]  channel-major, relu(W_ref.ref)
__device__ float g_V[BS * NTOK * C];     // [b][n][c]  token-major transpose of ref
__device__ float g_G[BS * C * NTOK];     // [b][c][n]  gate = W_out.tgt + b_out

// ---------------------------------------------------------------------------
// Projection: out[b][o][n0+n] = act( sum_c x[b][c][n0+n] * W[o][c] + bias[o] )
// Block: 256 threads, 64 tokens. Xs stored token-major [n][132] for vec4 reads.
// ---------------------------------------------------------------------------
template<int OC, bool RELU>
__global__ __launch_bounds__(256)
void proj_kernel(const float* __restrict__ x, const float* __restrict__ W,
                 const float* __restrict__ bias, float* __restrict__ out)
{
    extern __shared__ float sm[];
    float* Ws = sm;                 // OC*128
    float* Xs = sm + OC * 128;      // 64*132

    const int b   = blockIdx.y;
    const int n0  = blockIdx.x * 64;
    const int tid = threadIdx.x;

    for (int idx = tid; idx < OC * 128; idx += 256) Ws[idx] = W[idx];
    for (int idx = tid; idx < 128 * 64; idx += 256) {
        int c = idx >> 6, n = idx & 63;
        Xs[n * 132 + c] = x[((size_t)b * C + c) * NTOK + n0 + n];
    }
    __syncthreads();

    constexpr int JC = OC / 4;
    const int n  = tid & 63;
    const int og = tid >> 6;           // 0..3

    float acc[JC];
#pragma unroll
    for (int j = 0; j < JC; j++) acc[j] = bias[og * JC + j];

    for (int cc = 0; cc < 32; cc++) {
        float4 x4 = *(const float4*)&Xs[n * 132 + cc * 4];
#pragma unroll
        for (int j = 0; j < JC; j++) {
            float4 w4 = *(const float4*)&Ws[(og * JC + j) * 128 + cc * 4];
            acc[j] += x4.x * w4.x;
            acc[j] += x4.y * w4.y;
            acc[j] += x4.z * w4.z;
            acc[j] += x4.w * w4.w;
        }
    }

#pragma unroll
    for (int j = 0; j < JC; j++) {
        float v = RELU ? fmaxf(acc[j], 0.0f) : acc[j];
        out[((size_t)b * OC + og * JC + j) * NTOK + n0 + n] = v;
    }
}

// ---------------------------------------------------------------------------
// Transpose V: ref [b][c][n] -> g_V [b][n][c]
// ---------------------------------------------------------------------------
__global__ __launch_bounds__(256)
void transpose_v(const float* __restrict__ ref, float* __restrict__ Vb)
{
    __shared__ float t[32][33];
    const int b  = blockIdx.z;
    const int nb = blockIdx.x * 32;   // token block
    const int cb = blockIdx.y * 32;   // channel block
    const int tx = threadIdx.x, ty = threadIdx.y;

#pragma unroll
    for (int i = 0; i < 4; i++) {
        int c = cb + ty + i * 8;
        t[ty + i * 8][tx] = ref[((size_t)b * C + c) * NTOK + nb + tx];
    }
    __syncthreads();
#pragma unroll
    for (int i = 0; i < 4; i++) {
        Vb[((size_t)b * NTOK + nb + ty + i * 8) * C + cb + tx] = t[tx][ty + i * 8];
    }
}

// ---------------------------------------------------------------------------
// Flash attention + gate. Block: 256 threads, one 64-query tile of one batch.
//   scores: thread (sr=tid/16, sc=tid%16) owns rows sr*4..+3, keys sc+16j (j<4)
//   accum : same rows, cols sc*4..+3 and 64+sc*4..+3  (4x8 register tile)
// SMEM: Qs/Ks/Pm [64][68] (pad 68 -> conflict-free vec4 d/k reads), Vs [64][132]
// ---------------------------------------------------------------------------
__global__ __launch_bounds__(256, 2)
void attn_kernel(const float* __restrict__ Qb, const float* __restrict__ Kb,
                 const float* __restrict__ Vb, const float* __restrict__ Gb,
                 float* __restrict__ out)
{
    extern __shared__ float sm[];
    float* Qs = sm;                  // 64*68
    float* Ks = Qs + 64 * 68;        // 64*68
    float* Pm = Ks + 64 * 68;        // 64*68
    float* Vs = Pm + 64 * 68;        // 64*132

    const int b   = blockIdx.y;
    const int n0  = blockIdx.x * TM;
    const int tid = threadIdx.x;
    const int sr  = tid >> 4;        // 0..15
    const int sc  = tid & 15;        // 0..15
    const int row0 = sr * 4;

    // Q tile: Qb is [b][d][n] -> Qs[r][d]
    for (int idx = tid; idx < TM * CH; idx += 256) {
        int d = idx >> 6, r = idx & 63;
        Qs[r * 68 + d] = Qb[((size_t)b * CH + d) * NTOK + n0 + r];
    }

    float acc[32];
#pragma unroll
    for (int i = 0; i < 32; i++) acc[i] = 0.0f;
    float mrow[4] = {-1e30f, -1e30f, -1e30f, -1e30f};
    float lrow[4] = {0.f, 0.f, 0.f, 0.f};

    for (int kt = 0; kt < NTOK / TN; kt++) {
        const int k0 = kt * TN;
        __syncthreads();   // previous accumulate done reading Ks/Vs/Pm

        for (int idx = tid; idx < TN * CH; idx += 256) {
            int d = idx >> 6, k = idx & 63;
            Ks[k * 68 + d] = Kb[((size_t)b * CH + d) * NTOK + k0 + k];
        }
        for (int idx = tid; idx < TN * C; idx += 256) {
            int k = idx >> 7, c = idx & 127;
            Vs[k * 132 + c] = Vb[((size_t)b * NTOK + k0 + k) * C + c];
        }
        __syncthreads();

        // ----- scores: s[i][j] = Q[row0+i] . K[sc+16j] -----
        float s[16];
#pragma unroll
        for (int i = 0; i < 16; i++) s[i] = 0.0f;

        for (int dd = 0; dd < 16; dd++) {
            float4 q0 = *(const float4*)&Qs[(row0 + 0) * 68 + dd * 4];
            float4 q1 = *(const float4*)&Qs[(row0 + 1) * 68 + dd * 4];
            float4 q2 = *(const float4*)&Qs[(row0 + 2) * 68 + dd * 4];
            float4 q3 = *(const float4*)&Qs[(row0 + 3) * 68 + dd * 4];
#pragma unroll
            for (int j = 0; j < 4; j++) {
                float4 kv = *(const float4*)&Ks[(sc + 16 * j) * 68 + dd * 4];
                s[0 * 4 + j] += q0.x * kv.x; s[0 * 4 + j] += q0.y * kv.y;
                s[0 * 4 + j] += q0.z * kv.z; s[0 * 4 + j] += q0.w * kv.w;
                s[1 * 4 + j] += q1.x * kv.x; s[1 * 4 + j] += q1.y * kv.y;
                s[1 * 4 + j] += q1.z * kv.z; s[1 * 4 + j] += q1.w * kv.w;
                s[2 * 4 + j] += q2.x * kv.x; s[2 * 4 + j] += q2.y * kv.y;
                s[2 * 4 + j] += q2.z * kv.z; s[2 * 4 + j] += q2.w * kv.w;
                s[3 * 4 + j] += q3.x * kv.x; s[3 * 4 + j] += q3.y * kv.y;
                s[3 * 4 + j] += q3.z * kv.z; s[3 * 4 + j] += q3.w * kv.w;
            }
        }

        // ----- online softmax (16 threads per row group, half-warp shfl) -----
        float corr[4];
#pragma unroll
        for (int i = 0; i < 4; i++) {
            float m = fmaxf(fmaxf(s[i * 4 + 0], s[i * 4 + 1]),
                            fmaxf(s[i * 4 + 2], s[i * 4 + 3]));
            m = fmaxf(m, __shfl_xor_sync(0xffffffffu, m, 1));
            m = fmaxf(m, __shfl_xor_sync(0xffffffffu, m, 2));
            m = fmaxf(m, __shfl_xor_sync(0xffffffffu, m, 4));
            m = fmaxf(m, __shfl_xor_sync(0xffffffffu, m, 8));
            float mnew = fmaxf(mrow[i], m);
            corr[i] = __expf(mrow[i] - mnew);
            float ps = 0.0f;
#pragma unroll
            for (int j = 0; j < 4; j++) {
                float p = __expf(s[i * 4 + j] - mnew);
                ps += p;
                Pm[(row0 + i) * 68 + sc + 16 * j] = p;
            }
            ps += __shfl_xor_sync(0xffffffffu, ps, 1);
            ps += __shfl_xor_sync(0xffffffffu, ps, 2);
            ps += __shfl_xor_sync(0xffffffffu, ps, 4);
            ps += __shfl_xor_sync(0xffffffffu, ps, 8);
            lrow[i] = lrow[i] * corr[i] + ps;
            mrow[i] = mnew;
        }
#pragma unroll
        for (int i = 0; i < 4; i++)
#pragma unroll
            for (int c = 0; c < 8; c++) acc[i * 8 + c] *= corr[i];

        __syncthreads();   // Pm fully written

        // ----- accumulate: O[rows][cols] += P . V -----
        for (int k4 = 0; k4 < 16; k4++) {
            float pr[16];
#pragma unroll
            for (int i = 0; i < 4; i++)
                *(float4*)&pr[i * 4] = *(const float4*)&Pm[(row0 + i) * 68 + k4 * 4];
#pragma unroll
            for (int t = 0; t < 4; t++) {
                const float* vp = &Vs[(k4 * 4 + t) * 132 + sc * 4];
                float4 va = *(const float4*)vp;
                float4 vb = *(const float4*)(vp + 64);
#pragma unroll
                for (int i = 0; i < 4; i++) {
                    float p = pr[i * 4 + t];
                    acc[i * 8 + 0] += p * va.x; acc[i * 8 + 1] += p * va.y;
                    acc[i * 8 + 2] += p * va.z; acc[i * 8 + 3] += p * va.w;
                    acc[i * 8 + 4] += p * vb.x; acc[i * 8 + 5] += p * vb.y;
                    acc[i * 8 + 6] += p * vb.z; acc[i * 8 + 7] += p * vb.w;
                }
            }
        }
    }

    // ----- epilogue: normalize, stage through SMEM, gate, coalesced store -----
    __syncthreads();
#pragma unroll
    for (int i = 0; i < 4; i++) {
        float inv = 1.0f / lrow[i];
        float4 oa = make_float4(acc[i * 8 + 0] * inv, acc[i * 8 + 1] * inv,
                                acc[i * 8 + 2] * inv, acc[i * 8 + 3] * inv);
        float4 ob = make_float4(acc[i * 8 + 4] * inv, acc[i * 8 + 5] * inv,
                                acc[i * 8 + 6] * inv, acc[i * 8 + 7] * inv);
        *(float4*)&Vs[(row0 + i) * 132 + sc * 4]      = oa;
        *(float4*)&Vs[(row0 + i) * 132 + 64 + sc * 4] = ob;
    }
    __syncthreads();
    for (int idx = tid; idx < TM * C; idx += 256) {
        int c = idx >> 6, n = idx & 63;
        size_t g = ((size_t)b * C + c) * NTOK + n0 + n;
        out[g] = Vs[n * 132 + c] * Gb[g];
    }
}

// ---------------------------------------------------------------------------
extern "C" void kernel_launch(void* const* d_in, const int* in_sizes, int n_in,
                              void* d_out, int out_size)
{
    const float* tgt   = (const float*)d_in[0];
    const float* refp  = (const float*)d_in[1];
    const float* W_tgt = (const float*)d_in[2];
    const float* b_tgt = (const float*)d_in[3];
    const float* W_ref = (const float*)d_in[4];
    const float* b_ref = (const float*)d_in[5];
    const float* W_out = (const float*)d_in[6];
    const float* b_out = (const float*)d_in[7];
    float* out = (float*)d_out;

    float *qp, *kp, *vp, *gp;
    cudaGetSymbolAddress((void**)&qp, g_Q);
    cudaGetSymbolAddress((void**)&kp, g_K);
    cudaGetSymbolAddress((void**)&vp, g_V);
    cudaGetSymbolAddress((void**)&gp, g_G);

    const int smemQK = (64 * 128 + 64 * 132) * 4;        // 66560
    const int smemG  = (128 * 128 + 64 * 132) * 4;       // 99328
    const int smemA  = (3 * 64 * 68 + 64 * 132) * 4;     // 86016

    cudaFuncSetAttribute(proj_kernel<64, true>,
                         cudaFuncAttributeMaxDynamicSharedMemorySize, smemQK);
    cudaFuncSetAttribute(proj_kernel<128, false>,
                         cudaFuncAttributeMaxDynamicSharedMemorySize, smemG);
    cudaFuncSetAttribute(attn_kernel,
                         cudaFuncAttributeMaxDynamicSharedMemorySize, smemA);

    dim3 pg(NTOK / 64, BS);
    proj_kernel<64, true ><<<pg, 256, smemQK>>>(tgt,  W_tgt, b_tgt, qp);
    proj_kernel<64, true ><<<pg, 256, smemQK>>>(refp, W_ref, b_ref, kp);
    proj_kernel<128, false><<<pg, 256, smemG >>>(tgt,  W_out, b_out, gp);
    transpose_v<<<dim3(NTOK / 32, C / 32, BS), dim3(32, 8)>>>(refp, vp);
    attn_kernel<<<pg, 256, smemA>>>(qp, kp, vp, gp, out);
}

// round 2
// speedup vs baseline: 1.0292x; 1.0292x over previous
#include <cuda_runtime.h>
#include <math.h>

// Shapes (fixed for this problem)
#define BS   8
#define C    128
#define CH   64
#define NTOK 4096   // 64*64 tokens
#define TM   64     // query tile
#define TN   64     // key tile

// Scratch (static device memory — no allocation in kernel_launch)
__device__ float g_Q[BS * CH * NTOK];    // [b][d][n]  channel-major, relu(W_tgt.tgt)
__device__ float g_K[BS * CH * NTOK];    // [b][d][n]  channel-major, relu(W_ref.ref)
__device__ float g_V[BS * NTOK * C];     // [b][n][c]  token-major transpose of ref
__device__ float g_G[BS * C * NTOK];     // [b][c][n]  gate = W_out.tgt + b_out

// ---------------------------------------------------------------------------
// Packed fp32x2 helpers (Blackwell FFMA2 — only reachable via PTX f32x2 ops)
// ---------------------------------------------------------------------------
__device__ __forceinline__ void fma2(unsigned long long& d,
                                     unsigned long long a, unsigned long long b) {
    asm("fma.rn.f32x2 %0, %1, %2, %0;" : "+l"(d) : "l"(a), "l"(b));
}
__device__ __forceinline__ void mul2(unsigned long long& d, unsigned long long a) {
    asm("mul.rn.f32x2 %0, %0, %1;" : "+l"(d) : "l"(a));
}
__device__ __forceinline__ unsigned long long pack2(float x) {
    unsigned long long r;
    unsigned u = __float_as_uint(x);
    asm("mov.b64 %0, {%1, %1};" : "=l"(r) : "r"(u));
    return r;
}
__device__ __forceinline__ float sum2(unsigned long long v) {
    return __uint_as_float((unsigned)v) + __uint_as_float((unsigned)(v >> 32));
}
__device__ __forceinline__ float2 unpk2(unsigned long long v) {
    return make_float2(__uint_as_float((unsigned)v),
                       __uint_as_float((unsigned)(v >> 32)));
}

// ---------------------------------------------------------------------------
// Projection: out[b][o][n0+n] = act( sum_c x[b][c][n0+n] * W[o][c] + bias[o] )
// FMA2: accumulator lanes hold (even-c, odd-c) partial dot products.
// ---------------------------------------------------------------------------
template<int OC, bool RELU>
__global__ __launch_bounds__(256)
void proj_kernel(const float* __restrict__ x, const float* __restrict__ W,
                 const float* __restrict__ bias, float* __restrict__ out)
{
    extern __shared__ float sm[];
    float* Ws = sm;                 // OC*128
    float* Xs = sm + OC * 128;      // 64*132

    const int b   = blockIdx.y;
    const int n0  = blockIdx.x * 64;
    const int tid = threadIdx.x;

    for (int idx = tid; idx < OC * 128; idx += 256) Ws[idx] = W[idx];
    for (int idx = tid; idx < 128 * 64; idx += 256) {
        int c = idx >> 6, n = idx & 63;
        Xs[n * 132 + c] = x[((size_t)b * C + c) * NTOK + n0 + n];
    }
    __syncthreads();

    constexpr int JC = OC / 4;
    const int n  = tid & 63;
    const int og = tid >> 6;           // 0..3

    unsigned long long acc2[JC];
#pragma unroll
    for (int j = 0; j < JC; j++) acc2[j] = 0ull;

    for (int cc = 0; cc < 32; cc++) {
        ulonglong2 x2 = *(const ulonglong2*)&Xs[n * 132 + cc * 4];
#pragma unroll
        for (int j = 0; j < JC; j++) {
            ulonglong2 w2 = *(const ulonglong2*)&Ws[(og * JC + j) * 128 + cc * 4];
            fma2(acc2[j], x2.x, w2.x);
            fma2(acc2[j], x2.y, w2.y);
        }
    }

#pragma unroll
    for (int j = 0; j < JC; j++) {
        float v = sum2(acc2[j]) + bias[og * JC + j];
        if (RELU) v = fmaxf(v, 0.0f);
        out[((size_t)b * OC + og * JC + j) * NTOK + n0 + n] = v;
    }
}

// ---------------------------------------------------------------------------
// Transpose V: ref [b][c][n] -> g_V [b][n][c]
// ---------------------------------------------------------------------------
__global__ __launch_bounds__(256)
void transpose_v(const float* __restrict__ ref, float* __restrict__ Vb)
{
    __shared__ float t[32][33];
    const int b  = blockIdx.z;
    const int nb = blockIdx.x * 32;
    const int cb = blockIdx.y * 32;
    const int tx = threadIdx.x, ty = threadIdx.y;

#pragma unroll
    for (int i = 0; i < 4; i++) {
        int c = cb + ty + i * 8;
        t[ty + i * 8][tx] = ref[((size_t)b * C + c) * NTOK + nb + tx];
    }
    __syncthreads();
#pragma unroll
    for (int i = 0; i < 4; i++) {
        Vb[((size_t)b * NTOK + nb + ty + i * 8) * C + cb + tx] = t[tx][ty + i * 8];
    }
}

// ---------------------------------------------------------------------------
// Flash attention + gate, FFMA2 version. 256 threads / 64-query tile / batch.
//   scores: lanes = (even-d, odd-d) partials; final lo+hi reduce.
//   AV:     lanes = (c, c+1) channel pairs; P broadcast-packed per (row,k).
// SMEM: Qs/Ks/Pm [64][68], Vs [64][132]
// ---------------------------------------------------------------------------
__global__ __launch_bounds__(256, 2)
void attn_kernel(const float* __restrict__ Qb, const float* __restrict__ Kb,
                 const float* __restrict__ Vb, const float* __restrict__ Gb,
                 float* __restrict__ out)
{
    extern __shared__ float sm[];
    float* Qs = sm;                  // 64*68
    float* Ks = Qs + 64 * 68;        // 64*68
    float* Pm = Ks + 64 * 68;        // 64*68
    float* Vs = Pm + 64 * 68;        // 64*132

    const int b   = blockIdx.y;
    const int n0  = blockIdx.x * TM;
    const int tid = threadIdx.x;
    const int sr  = tid >> 4;        // 0..15
    const int sc  = tid & 15;        // 0..15
    const int row0 = sr * 4;

    for (int idx = tid; idx < TM * CH; idx += 256) {
        int d = idx >> 6, r = idx & 63;
        Qs[r * 68 + d] = Qb[((size_t)b * CH + d) * NTOK + n0 + r];
    }

    // acc2[i*4+cp]: row i, channel-pair cp: {sc*4, sc*4+2, 64+sc*4, 64+sc*4+2}
    unsigned long long acc2[16];
#pragma unroll
    for (int i = 0; i < 16; i++) acc2[i] = 0ull;
    float mrow[4] = {-1e30f, -1e30f, -1e30f, -1e30f};
    float lrow[4] = {0.f, 0.f, 0.f, 0.f};

    for (int kt = 0; kt < NTOK / TN; kt++) {
        const int k0 = kt * TN;
        __syncthreads();

        for (int idx = tid; idx < TN * CH; idx += 256) {
            int d = idx >> 6, k = idx & 63;
            Ks[k * 68 + d] = Kb[((size_t)b * CH + d) * NTOK + k0 + k];
        }
        for (int idx = tid; idx < TN * C; idx += 256) {
            int k = idx >> 7, c = idx & 127;
            Vs[k * 132 + c] = Vb[((size_t)b * NTOK + k0 + k) * C + c];
        }
        __syncthreads();

        // ----- scores: s2 lanes = (even-d, odd-d) partials -----
        unsigned long long s2[16];
#pragma unroll
        for (int i = 0; i < 16; i++) s2[i] = 0ull;

#pragma unroll 4
        for (int dd = 0; dd < 16; dd++) {
            ulonglong2 q0 = *(const ulonglong2*)&Qs[(row0 + 0) * 68 + dd * 4];
            ulonglong2 q1 = *(const ulonglong2*)&Qs[(row0 + 1) * 68 + dd * 4];
            ulonglong2 q2 = *(const ulonglong2*)&Qs[(row0 + 2) * 68 + dd * 4];
            ulonglong2 q3 = *(const ulonglong2*)&Qs[(row0 + 3) * 68 + dd * 4];
#pragma unroll
            for (int j = 0; j < 4; j++) {
                ulonglong2 kv = *(const ulonglong2*)&Ks[(sc + 16 * j) * 68 + dd * 4];
                fma2(s2[0 * 4 + j], q0.x, kv.x); fma2(s2[0 * 4 + j], q0.y, kv.y);
                fma2(s2[1 * 4 + j], q1.x, kv.x); fma2(s2[1 * 4 + j], q1.y, kv.y);
                fma2(s2[2 * 4 + j], q2.x, kv.x); fma2(s2[2 * 4 + j], q2.y, kv.y);
                fma2(s2[3 * 4 + j], q3.x, kv.x); fma2(s2[3 * 4 + j], q3.y, kv.y);
            }
        }
        float s[16];
#pragma unroll
        for (int e = 0; e < 16; e++) s[e] = sum2(s2[e]);

        // ----- online softmax -----
        float corr[4];
#pragma unroll
        for (int i = 0; i < 4; i++) {
            float m = fmaxf(fmaxf(s[i * 4 + 0], s[i * 4 + 1]),
                            fmaxf(s[i * 4 + 2], s[i * 4 + 3]));
            m = fmaxf(m, __shfl_xor_sync(0xffffffffu, m, 1));
            m = fmaxf(m, __shfl_xor_sync(0xffffffffu, m, 2));
            m = fmaxf(m, __shfl_xor_sync(0xffffffffu, m, 4));
            m = fmaxf(m, __shfl_xor_sync(0xffffffffu, m, 8));
            float mnew = fmaxf(mrow[i], m);
            corr[i] = __expf(mrow[i] - mnew);
            float ps = 0.0f;
#pragma unroll
            for (int j = 0; j < 4; j++) {
                float p = __expf(s[i * 4 + j] - mnew);
                ps += p;
                Pm[(row0 + i) * 68 + sc + 16 * j] = p;
            }
            ps += __shfl_xor_sync(0xffffffffu, ps, 1);
            ps += __shfl_xor_sync(0xffffffffu, ps, 2);
            ps += __shfl_xor_sync(0xffffffffu, ps, 4);
            ps += __shfl_xor_sync(0xffffffffu, ps, 8);
            lrow[i] = lrow[i] * corr[i] + ps;
            mrow[i] = mnew;
        }
#pragma unroll
        for (int i = 0; i < 4; i++) {
            unsigned long long c2 = pack2(corr[i]);
#pragma unroll
            for (int cp = 0; cp < 4; cp++) mul2(acc2[i * 4 + cp], c2);
        }

        __syncthreads();   // Pm fully written

        // ----- accumulate: O += P . V  (c-pair lanes) -----
        for (int k4 = 0; k4 < 16; k4++) {
            float pr[16];
#pragma unroll
            for (int i = 0; i < 4; i++)
                *(float4*)&pr[i * 4] = *(const float4*)&Pm[(row0 + i) * 68 + k4 * 4];
#pragma unroll
            for (int t = 0; t < 4; t++) {
                const float* vp = &Vs[(k4 * 4 + t) * 132 + sc * 4];
                ulonglong2 va = *(const ulonglong2*)vp;          // (c0,c1),(c2,c3)
                ulonglong2 vb = *(const ulonglong2*)(vp + 64);   // +64 channels
#pragma unroll
                for (int i = 0; i < 4; i++) {
                    unsigned long long p2 = pack2(pr[i * 4 + t]);
                    fma2(acc2[i * 4 + 0], p2, va.x);
                    fma2(acc2[i * 4 + 1], p2, va.y);
                    fma2(acc2[i * 4 + 2], p2, vb.x);
                    fma2(acc2[i * 4 + 3], p2, vb.y);
                }
            }
        }
    }

    // ----- epilogue: normalize, stage through SMEM, gate, coalesced store -----
    __syncthreads();
#pragma unroll
    for (int i = 0; i < 4; i++) {
        float inv = 1.0f / lrow[i];
        float2 a0 = unpk2(acc2[i * 4 + 0]);
        float2 a1 = unpk2(acc2[i * 4 + 1]);
        float2 a2 = unpk2(acc2[i * 4 + 2]);
        float2 a3 = unpk2(acc2[i * 4 + 3]);
        float4 oa = make_float4(a0.x * inv, a0.y * inv, a1.x * inv, a1.y * inv);
        float4 ob = make_float4(a2.x * inv, a2.y * inv, a3.x * inv, a3.y * inv);
        *(float4*)&Vs[(row0 + i) * 132 + sc * 4]      = oa;
        *(float4*)&Vs[(row0 + i) * 132 + 64 + sc * 4] = ob;
    }
    __syncthreads();
    for (int idx = tid; idx < TM * C; idx += 256) {
        int c = idx >> 6, n = idx & 63;
        size_t g = ((size_t)b * C + c) * NTOK + n0 + n;
        out[g] = Vs[n * 132 + c] * Gb[g];
    }
}

// ---------------------------------------------------------------------------
extern "C" void kernel_launch(void* const* d_in, const int* in_sizes, int n_in,
                              void* d_out, int out_size)
{
    const float* tgt   = (const float*)d_in[0];
    const float* refp  = (const float*)d_in[1];
    const float* W_tgt = (const float*)d_in[2];
    const float* b_tgt = (const float*)d_in[3];
    const float* W_ref = (const float*)d_in[4];
    const float* b_ref = (const float*)d_in[5];
    const float* W_out = (const float*)d_in[6];
    const float* b_out = (const float*)d_in[7];
    float* out = (float*)d_out;

    float *qp, *kp, *vp, *gp;
    cudaGetSymbolAddress((void**)&qp, g_Q);
    cudaGetSymbolAddress((void**)&kp, g_K);
    cudaGetSymbolAddress((void**)&vp, g_V);
    cudaGetSymbolAddress((void**)&gp, g_G);

    const int smemQK = (64 * 128 + 64 * 132) * 4;        // 66560
    const int smemG  = (128 * 128 + 64 * 132) * 4;       // 99328
    const int smemA  = (3 * 64 * 68 + 64 * 132) * 4;     // 86016

    cudaFuncSetAttribute(proj_kernel<64, true>,
                         cudaFuncAttributeMaxDynamicSharedMemorySize, smemQK);
    cudaFuncSetAttribute(proj_kernel<128, false>,
                         cudaFuncAttributeMaxDynamicSharedMemorySize, smemG);
    cudaFuncSetAttribute(attn_kernel,
                         cudaFuncAttributeMaxDynamicSharedMemorySize, smemA);

    dim3 pg(NTOK / 64, BS);
    proj_kernel<64, true ><<<pg, 256, smemQK>>>(tgt,  W_tgt, b_tgt, qp);
    proj_kernel<64, true ><<<pg, 256, smemQK>>>(refp, W_ref, b_ref, kp);
    proj_kernel<128, false><<<pg, 256, smemG >>>(tgt,  W_out, b_out, gp);
    transpose_v<<<dim3(NTOK / 32, C / 32, BS), dim3(32, 8)>>>(refp, vp);
    attn_kernel<<<pg, 256, smemA>>>(qp, kp, vp, gp, out);
}

// round 5
// speedup vs baseline: 2.2052x; 2.1427x over previous
#include <cuda_runtime.h>
#include <cuda_bf16.h>
#include <math.h>
#include <stdint.h>

// Shapes (fixed)
#define BS    8
#define C     128
#define CH    64
#define NTOK  4096
#define TQ    128       // queries per CTA (8 warps x 16 rows)
#define TK    64        // keys per k-tile
#define KTILES (NTOK/TK)

// SMEM row stride for bf16 tiles: 72 elements = 144B (16B aligned, ldmatrix
// rows land on banks 4i%32 -> conflict-free)
#define RS    72

// ---------------------------------------------------------------------------
// Static scratch
// ---------------------------------------------------------------------------
__device__ __nv_bfloat16 g_Qhi[(size_t)BS * NTOK * CH];  // [b][n][d]
__device__ __nv_bfloat16 g_Qlo[(size_t)BS * NTOK * CH];
__device__ __nv_bfloat16 g_Khi[(size_t)BS * NTOK * CH];  // [b][n][d]
__device__ __nv_bfloat16 g_Klo[(size_t)BS * NTOK * CH];
__device__ __nv_bfloat16 g_Vhi[(size_t)BS * C * NTOK];   // [b][c][n]
__device__ __nv_bfloat16 g_Vlo[(size_t)BS * C * NTOK];
__device__ float         g_G  [(size_t)BS * C * NTOK];   // gate [b][c][n]

// ---------------------------------------------------------------------------
// PTX helpers (baseline ISA only — no sm_103a-gated instructions)
// ---------------------------------------------------------------------------
__device__ __forceinline__ uint32_t smem_u32(const void* p) {
    uint32_t a;
    asm("{ .reg .u64 t; cvta.to.shared.u64 t, %1; cvt.u32.u64 %0, t; }"
        : "=r"(a) : "l"(p));
    return a;
}
__device__ __forceinline__ void ldsm4(uint32_t* r, uint32_t a) {
    asm volatile("ldmatrix.sync.aligned.m8n8.x4.shared.b16 {%0,%1,%2,%3}, [%4];"
        : "=r"(r[0]), "=r"(r[1]), "=r"(r[2]), "=r"(r[3]) : "r"(a));
}
__device__ __forceinline__ void ldsm2(uint32_t* r, uint32_t a) {
    asm volatile("ldmatrix.sync.aligned.m8n8.x2.shared.b16 {%0,%1}, [%2];"
        : "=r"(r[0]), "=r"(r[1]) : "r"(a));
}
__device__ __forceinline__ void mma_bf16(float* d, const uint32_t* a, const uint32_t* b) {
    asm volatile("mma.sync.aligned.m16n8k16.row.col.f32.bf16.bf16.f32 "
        "{%0,%1,%2,%3},{%4,%5,%6,%7},{%8,%9},{%0,%1,%2,%3};"
        : "+f"(d[0]), "+f"(d[1]), "+f"(d[2]), "+f"(d[3])
        : "r"(a[0]), "r"(a[1]), "r"(a[2]), "r"(a[3]), "r"(b[0]), "r"(b[1]));
}
__device__ __forceinline__ uint32_t cvt2(float hi, float lo) {
    uint32_t r;
    asm("cvt.rn.bf16x2.f32 %0, %1, %2;" : "=r"(r) : "f"(hi), "f"(lo));
    return r;
}
__device__ __forceinline__ float lo_of(uint32_t h) { return __uint_as_float(h << 16); }
__device__ __forceinline__ float hi_of(uint32_t h) { return __uint_as_float(h & 0xffff0000u); }

// ---------------------------------------------------------------------------
// Projection for Q/K: relu(W.x + b), split to bf16 hi/lo, token-major [b][n][64]
// ---------------------------------------------------------------------------
__global__ __launch_bounds__(256)
void proj_qk(const float* __restrict__ x, const float* __restrict__ W,
             const float* __restrict__ bias,
             __nv_bfloat16* __restrict__ ohi, __nv_bfloat16* __restrict__ olo)
{
    extern __shared__ float smf[];
    float* Ws = smf;                 // 64*128
    float* Xs = smf + 64 * 128;      // 64*132

    const int b   = blockIdx.y;
    const int n0  = blockIdx.x * 64;
    const int tid = threadIdx.x;

    for (int idx = tid; idx < 64 * 128; idx += 256) Ws[idx] = W[idx];
    for (int idx = tid; idx < 128 * 64; idx += 256) {
        int c = idx >> 6, n = idx & 63;
        Xs[n * 132 + c] = x[((size_t)b * C + c) * NTOK + n0 + n];
    }
    __syncthreads();

    const int n  = tid & 63;
    const int og = tid >> 6;           // 0..3 -> outputs og*16..+15

    float acc[16];
#pragma unroll
    for (int j = 0; j < 16; j++) acc[j] = bias[og * 16 + j];
    for (int cc = 0; cc < 32; cc++) {
        float4 x4 = *(const float4*)&Xs[n * 132 + cc * 4];
#pragma unroll
        for (int j = 0; j < 16; j++) {
            float4 w4 = *(const float4*)&Ws[(og * 16 + j) * 128 + cc * 4];
            acc[j] += x4.x * w4.x; acc[j] += x4.y * w4.y;
            acc[j] += x4.z * w4.z; acc[j] += x4.w * w4.w;
        }
    }

    __align__(16) __nv_bfloat16 hb[16], lb[16];
#pragma unroll
    for (int j = 0; j < 16; j++) {
        float v = fmaxf(acc[j], 0.0f);
        __nv_bfloat16 h = __float2bfloat16(v);
        hb[j] = h;
        lb[j] = __float2bfloat16(v - __bfloat162float(h));
    }
    size_t base = ((size_t)b * NTOK + n0 + n) * CH + og * 16;
    *(uint4*)&ohi[base]     = ((const uint4*)hb)[0];
    *(uint4*)&ohi[base + 8] = ((const uint4*)hb)[1];
    *(uint4*)&olo[base]     = ((const uint4*)lb)[0];
    *(uint4*)&olo[base + 8] = ((const uint4*)lb)[1];
}

// ---------------------------------------------------------------------------
// Gate projection (fp32, channel-major)
// ---------------------------------------------------------------------------
__global__ __launch_bounds__(256)
void proj_gate(const float* __restrict__ x, const float* __restrict__ W,
               const float* __restrict__ bias, float* __restrict__ out)
{
    extern __shared__ float smg[];
    float* Ws = smg;                 // 128*128
    float* Xs = smg + 128 * 128;     // 64*132

    const int b   = blockIdx.y;
    const int n0  = blockIdx.x * 64;
    const int tid = threadIdx.x;

    for (int idx = tid; idx < 128 * 128; idx += 256) Ws[idx] = W[idx];
    for (int idx = tid; idx < 128 * 64; idx += 256) {
        int c = idx >> 6, n = idx & 63;
        Xs[n * 132 + c] = x[((size_t)b * C + c) * NTOK + n0 + n];
    }
    __syncthreads();

    const int n  = tid & 63;
    const int og = tid >> 6;

    float acc[32];
#pragma unroll
    for (int j = 0; j < 32; j++) acc[j] = bias[og * 32 + j];
    for (int cc = 0; cc < 32; cc++) {
        float4 x4 = *(const float4*)&Xs[n * 132 + cc * 4];
#pragma unroll
        for (int j = 0; j < 32; j++) {
            float4 w4 = *(const float4*)&Ws[(og * 32 + j) * 128 + cc * 4];
            acc[j] += x4.x * w4.x; acc[j] += x4.y * w4.y;
            acc[j] += x4.z * w4.z; acc[j] += x4.w * w4.w;
        }
    }
#pragma unroll
    for (int j = 0; j < 32; j++)
        out[((size_t)b * C + og * 32 + j) * NTOK + n0 + n] = acc[j];
}

// ---------------------------------------------------------------------------
// Split V (= ref, native [b][c][n]) into bf16 hi/lo
// ---------------------------------------------------------------------------
__global__ __launch_bounds__(256)
void split_v(const float* __restrict__ ref,
             __nv_bfloat16* __restrict__ vhi, __nv_bfloat16* __restrict__ vlo)
{
    size_t i = ((size_t)blockIdx.x * 256 + threadIdx.x) * 8;
    float4 a = *(const float4*)(ref + i);
    float4 b = *(const float4*)(ref + i + 4);
    float v[8] = {a.x, a.y, a.z, a.w, b.x, b.y, b.z, b.w};
    __align__(16) __nv_bfloat16 h[8], l[8];
#pragma unroll
    for (int j = 0; j < 8; j++) {
        h[j] = __float2bfloat16(v[j]);
        l[j] = __float2bfloat16(v[j] - __bfloat162float(h[j]));
    }
    *(uint4*)(vhi + i) = *(const uint4*)h;
    *(uint4*)(vlo + i) = *(const uint4*)l;
}

// ---------------------------------------------------------------------------
// mma.sync flash attention + gate.
//   CTA = (batch, 128-query tile), 8 warps x 16 rows. Online softmax.
// SMEM (57KB): Khi[64][72] Klo[64][72] Vhi[128][72] Vlo[128][72]
//   Q staging (start only) aliases the K/V region.
// ---------------------------------------------------------------------------
#define OFF_KH 0
#define OFF_KL 9216
#define OFF_VH 18432
#define OFF_VL 36864
#define SMEM_ATTN 55296
#define OFF_QH 0
#define OFF_QL 18432

__global__ __launch_bounds__(256, 1)
void attn_mma(const __nv_bfloat16* __restrict__ Qhi, const __nv_bfloat16* __restrict__ Qlo,
              const __nv_bfloat16* __restrict__ Khi, const __nv_bfloat16* __restrict__ Klo,
              const __nv_bfloat16* __restrict__ Vhi, const __nv_bfloat16* __restrict__ Vlo,
              const float* __restrict__ G, float* __restrict__ out)
{
    extern __shared__ __align__(16) char smc[];
    const uint32_t sb = smem_u32(smc);

    const int tid  = threadIdx.x;
    const int wid  = tid >> 5, lane = tid & 31;
    const int b    = blockIdx.y;
    const int n0   = blockIdx.x * TQ;
    const int rbase = wid * 16;

    // ---- stage Q (hi+lo) into aliased SMEM, pull A-fragments into registers ----
    {
        const uint4* qh = (const uint4*)(Qhi + ((size_t)b * NTOK + n0) * CH);
        const uint4* ql = (const uint4*)(Qlo + ((size_t)b * NTOK + n0) * CH);
        for (int i = tid; i < 1024; i += 256) {       // 128 rows x 8 uint4
            int r = i >> 3, j = i & 7;
            *(uint4*)(smc + OFF_QH + r * 144 + j * 16) = qh[i];
            *(uint4*)(smc + OFF_QL + r * 144 + j * 16) = ql[i];
        }
    }
    __syncthreads();

    uint32_t qa[4][4], qb[4][4];                      // Q hi / lo A-frags, 4 ksteps
    {
        const int ar = rbase + (lane & 15);
        const int ac = 8 * (lane >> 4);               // bf16 col offset within kstep
#pragma unroll
        for (int kk = 0; kk < 4; kk++) {
            uint32_t off = (uint32_t)(ar * RS + kk * 16 + ac) * 2;
            ldsm4(qa[kk], sb + OFF_QH + off);
            ldsm4(qb[kk], sb + OFF_QL + off);
        }
    }

    float o[16][4];
#pragma unroll
    for (int jn = 0; jn < 16; jn++)
#pragma unroll
        for (int e = 0; e < 4; e++) o[jn][e] = 0.0f;
    float mx0 = -1e30f, mx1 = -1e30f, ls0 = 0.0f, ls1 = 0.0f;

    const int bn  = lane & 7;                 // B-frag row within 8-row tile
    const int bk8 = 8 * ((lane >> 3) & 1);    // k-half select

    for (int t = 0; t < KTILES; t++) {
        __syncthreads();                       // everyone done reading K/V (or Q frags)
        // ---- copy K (hi+lo) and V (hi+lo) into SMEM ----
        {
            const uint4* kh = (const uint4*)(Khi + ((size_t)b * NTOK + t * TK) * CH);
            const uint4* kl = (const uint4*)(Klo + ((size_t)b * NTOK + t * TK) * CH);
            for (int i = tid; i < 512; i += 256) {    // 64 rows x 8 uint4
                int r = i >> 3, j = i & 7;
                *(uint4*)(smc + OFF_KH + r * 144 + j * 16) = kh[i];
                *(uint4*)(smc + OFF_KL + r * 144 + j * 16) = kl[i];
            }
            const __nv_bfloat16* vhp = Vhi + (size_t)b * C * NTOK + t * TK;
            const __nv_bfloat16* vlp = Vlo + (size_t)b * C * NTOK + t * TK;
            for (int i = tid; i < 1024; i += 256) {   // 128 rows x 8 uint4
                int c = i >> 3, j = i & 7;
                *(uint4*)(smc + OFF_VH + c * 144 + j * 16) =
                    *(const uint4*)(vhp + (size_t)c * NTOK + j * 8);
                *(uint4*)(smc + OFF_VL + c * 144 + j * 16) =
                    *(const uint4*)(vlp + (size_t)c * NTOK + j * 8);
            }
        }
        __syncthreads();

        // ---- S = Q.K^T with 3-term compensation ----
        float s[8][4];
#pragma unroll
        for (int j = 0; j < 8; j++)
#pragma unroll
            for (int e = 0; e < 4; e++) s[j][e] = 0.0f;

#pragma unroll
        for (int kk = 0; kk < 4; kk++) {
#pragma unroll
            for (int j = 0; j < 8; j++) {
                uint32_t kh2[2], kl2[2];
                uint32_t ka = sb + OFF_KH +
                    (uint32_t)((j * 8 + bn) * RS + kk * 16 + bk8) * 2;
                ldsm2(kh2, ka);
                ldsm2(kl2, ka + (OFF_KL - OFF_KH));
                mma_bf16(s[j], qa[kk], kh2);
                mma_bf16(s[j], qa[kk], kl2);
                mma_bf16(s[j], qb[kk], kh2);
            }
        }

        // ---- online softmax (rows r0 = lane/4, r1 = r0+8) ----
        float a0 = -1e30f, a1 = -1e30f;
#pragma unroll
        for (int j = 0; j < 8; j++) {
            a0 = fmaxf(a0, fmaxf(s[j][0], s[j][1]));
            a1 = fmaxf(a1, fmaxf(s[j][2], s[j][3]));
        }
        a0 = fmaxf(a0, __shfl_xor_sync(0xffffffffu, a0, 1));
        a0 = fmaxf(a0, __shfl_xor_sync(0xffffffffu, a0, 2));
        a1 = fmaxf(a1, __shfl_xor_sync(0xffffffffu, a1, 1));
        a1 = fmaxf(a1, __shfl_xor_sync(0xffffffffu, a1, 2));
        float mn0 = fmaxf(mx0, a0), mn1 = fmaxf(mx1, a1);
        float cr0 = __expf(mx0 - mn0), cr1 = __expf(mx1 - mn1);
        float ps0 = 0.0f, ps1 = 0.0f;
#pragma unroll
        for (int j = 0; j < 8; j++) {
            s[j][0] = __expf(s[j][0] - mn0); ps0 += s[j][0];
            s[j][1] = __expf(s[j][1] - mn0); ps0 += s[j][1];
            s[j][2] = __expf(s[j][2] - mn1); ps1 += s[j][2];
            s[j][3] = __expf(s[j][3] - mn1); ps1 += s[j][3];
        }
        ps0 += __shfl_xor_sync(0xffffffffu, ps0, 1);
        ps0 += __shfl_xor_sync(0xffffffffu, ps0, 2);
        ps1 += __shfl_xor_sync(0xffffffffu, ps1, 1);
        ps1 += __shfl_xor_sync(0xffffffffu, ps1, 2);
        ls0 = ls0 * cr0 + ps0;  ls1 = ls1 * cr1 + ps1;
        mx0 = mn0;  mx1 = mn1;
#pragma unroll
        for (int jn = 0; jn < 16; jn++) {
            o[jn][0] *= cr0; o[jn][1] *= cr0;
            o[jn][2] *= cr1; o[jn][3] *= cr1;
        }

        // ---- P -> bf16 hi/lo A-fragments (pure register remap) ----
        uint32_t ph[4][4], pl[4][4];
#pragma unroll
        for (int kk = 0; kk < 4; kk++) {
            int j0 = 2 * kk, j1 = 2 * kk + 1;
            ph[kk][0] = cvt2(s[j0][1], s[j0][0]);
            ph[kk][1] = cvt2(s[j0][3], s[j0][2]);
            ph[kk][2] = cvt2(s[j1][1], s[j1][0]);
            ph[kk][3] = cvt2(s[j1][3], s[j1][2]);
            pl[kk][0] = cvt2(s[j0][1] - hi_of(ph[kk][0]), s[j0][0] - lo_of(ph[kk][0]));
            pl[kk][1] = cvt2(s[j0][3] - hi_of(ph[kk][1]), s[j0][2] - lo_of(ph[kk][1]));
            pl[kk][2] = cvt2(s[j1][1] - hi_of(ph[kk][2]), s[j1][0] - lo_of(ph[kk][2]));
            pl[kk][3] = cvt2(s[j1][3] - hi_of(ph[kk][3]), s[j1][2] - lo_of(ph[kk][3]));
        }

        // ---- O += P.V with 3-term compensation ----
#pragma unroll
        for (int kk = 0; kk < 4; kk++) {
#pragma unroll
            for (int jn = 0; jn < 16; jn++) {
                uint32_t vh2[2], vl2[2];
                uint32_t va = sb + OFF_VH +
                    (uint32_t)((jn * 8 + bn) * RS + kk * 16 + bk8) * 2;
                ldsm2(vh2, va);
                ldsm2(vl2, va + (OFF_VL - OFF_VH));
                mma_bf16(o[jn], ph[kk], vh2);
                mma_bf16(o[jn], ph[kk], vl2);
                mma_bf16(o[jn], pl[kk], vh2);
            }
        }
    }

    // ---- epilogue: normalize, gate, store ----
    const float inv0 = 1.0f / ls0, inv1 = 1.0f / ls1;
    const int tok = n0 + rbase + (lane >> 2);
#pragma unroll
    for (int jn = 0; jn < 16; jn++) {
        int c = jn * 8 + 2 * (lane & 3);
        size_t g = ((size_t)b * C + c) * NTOK + tok;
        out[g]            = o[jn][0] * inv0 * G[g];
        out[g + NTOK]     = o[jn][1] * inv0 * G[g + NTOK];
        out[g + 8]        = o[jn][2] * inv1 * G[g + 8];
        out[g + NTOK + 8] = o[jn][3] * inv1 * G[g + NTOK + 8];
    }
}

// ---------------------------------------------------------------------------
extern "C" void kernel_launch(void* const* d_in, const int* in_sizes, int n_in,
                              void* d_out, int out_size)
{
    const float* tgt   = (const float*)d_in[0];
    const float* refp  = (const float*)d_in[1];
    const float* W_tgt = (const float*)d_in[2];
    const float* b_tgt = (const float*)d_in[3];
    const float* W_ref = (const float*)d_in[4];
    const float* b_ref = (const float*)d_in[5];
    const float* W_out = (const float*)d_in[6];
    const float* b_out = (const float*)d_in[7];
    float* out = (float*)d_out;

    __nv_bfloat16 *qh, *ql, *kh, *kl, *vh, *vl; float* gp;
    cudaGetSymbolAddress((void**)&qh, g_Qhi);
    cudaGetSymbolAddress((void**)&ql, g_Qlo);
    cudaGetSymbolAddress((void**)&kh, g_Khi);
    cudaGetSymbolAddress((void**)&kl, g_Klo);
    cudaGetSymbolAddress((void**)&vh, g_Vhi);
    cudaGetSymbolAddress((void**)&vl, g_Vlo);
    cudaGetSymbolAddress((void**)&gp, g_G);

    const int smemQK = (64 * 128 + 64 * 132) * 4;
    const int smemG  = (128 * 128 + 64 * 132) * 4;

    cudaFuncSetAttribute(proj_qk,   cudaFuncAttributeMaxDynamicSharedMemorySize, smemQK);
    cudaFuncSetAttribute(proj_gate, cudaFuncAttributeMaxDynamicSharedMemorySize, smemG);
    cudaFuncSetAttribute(attn_mma,  cudaFuncAttributeMaxDynamicSharedMemorySize, SMEM_ATTN);

    dim3 pg(NTOK / 64, BS);
    proj_qk  <<<pg, 256, smemQK>>>(tgt,  W_tgt, b_tgt, qh, ql);
    proj_qk  <<<pg, 256, smemQK>>>(refp, W_ref, b_ref, kh, kl);
    proj_gate<<<pg, 256, smemG >>>(tgt,  W_out, b_out, gp);
    split_v<<<(BS * C * NTOK) / (256 * 8), 256>>>(refp, vh, vl);

    attn_mma<<<dim3(NTOK / TQ, BS), 256, SMEM_ATTN>>>(qh, ql, kh, kl, vh, vl, gp, out);
}

// round 6
// speedup vs baseline: 3.4725x; 1.5747x over previous
#include <cuda_runtime.h>
#include <cuda_fp16.h>
#include <math.h>
#include <stdint.h>

// Shapes (fixed)
#define BS    8
#define C     128
#define CH    64
#define NTOK  4096
#define TQ    128       // queries per CTA (8 warps x 16 rows)
#define TK    64        // keys per k-tile
#define KTILES (NTOK/TK)
#define RS    72        // SMEM row stride (fp16 elems): 144B, ldmatrix conflict-free

// ---------------------------------------------------------------------------
// Static scratch (fp16 hi/lo splits)
// ---------------------------------------------------------------------------
__device__ __half g_Qhi[(size_t)BS * NTOK * CH];  // [b][n][d]
__device__ __half g_Qlo[(size_t)BS * NTOK * CH];
__device__ __half g_Khi[(size_t)BS * NTOK * CH];  // [b][n][d]
__device__ __half g_Klo[(size_t)BS * NTOK * CH];
__device__ __half g_Vhi[(size_t)BS * C * NTOK];   // [b][c][n]
__device__ __half g_Vlo[(size_t)BS * C * NTOK];
__device__ float  g_G  [(size_t)BS * C * NTOK];   // gate [b][c][n]

// ---------------------------------------------------------------------------
// PTX helpers (baseline ISA: ldmatrix / mma.sync / cp.async)
// ---------------------------------------------------------------------------
__device__ __forceinline__ uint32_t smem_u32(const void* p) {
    uint32_t a;
    asm("{ .reg .u64 t; cvta.to.shared.u64 t, %1; cvt.u32.u64 %0, t; }"
        : "=r"(a) : "l"(p));
    return a;
}
__device__ __forceinline__ void ldsm4(uint32_t* r, uint32_t a) {
    asm volatile("ldmatrix.sync.aligned.m8n8.x4.shared.b16 {%0,%1,%2,%3}, [%4];"
        : "=r"(r[0]), "=r"(r[1]), "=r"(r[2]), "=r"(r[3]) : "r"(a));
}
__device__ __forceinline__ void ldsm2(uint32_t* r, uint32_t a) {
    asm volatile("ldmatrix.sync.aligned.m8n8.x2.shared.b16 {%0,%1}, [%2];"
        : "=r"(r[0]), "=r"(r[1]) : "r"(a));
}
__device__ __forceinline__ void mma_f16(float* d, const uint32_t* a, const uint32_t* b) {
    asm volatile("mma.sync.aligned.m16n8k16.row.col.f32.f16.f16.f32 "
        "{%0,%1,%2,%3},{%4,%5,%6,%7},{%8,%9},{%0,%1,%2,%3};"
        : "+f"(d[0]), "+f"(d[1]), "+f"(d[2]), "+f"(d[3])
        : "r"(a[0]), "r"(a[1]), "r"(a[2]), "r"(a[3]), "r"(b[0]), "r"(b[1]));
}
__device__ __forceinline__ uint32_t cvt2h(float hi, float lo) {
    uint32_t r;
    asm("cvt.rn.f16x2.f32 %0, %1, %2;" : "=r"(r) : "f"(hi), "f"(lo));
    return r;
}
__device__ __forceinline__ void cpa16(uint32_t dst, const void* src) {
    asm volatile("cp.async.cg.shared.global [%0], [%1], 16;" :: "r"(dst), "l"(src));
}
#define CP_COMMIT() asm volatile("cp.async.commit_group;" ::: "memory")
#define CP_WAIT1()  asm volatile("cp.async.wait_group 1;" ::: "memory")

// ---------------------------------------------------------------------------
// Projection for Q/K: relu(W.x + b), split to fp16 hi/lo, token-major [b][n][64]
// ---------------------------------------------------------------------------
__global__ __launch_bounds__(256)
void proj_qk(const float* __restrict__ x, const float* __restrict__ W,
             const float* __restrict__ bias,
             __half* __restrict__ ohi, __half* __restrict__ olo)
{
    extern __shared__ float smf[];
    float* Ws = smf;                 // 64*128
    float* Xs = smf + 64 * 128;      // 64*132

    const int b   = blockIdx.y;
    const int n0  = blockIdx.x * 64;
    const int tid = threadIdx.x;

    for (int idx = tid; idx < 64 * 128; idx += 256) Ws[idx] = W[idx];
    for (int idx = tid; idx < 128 * 64; idx += 256) {
        int c = idx >> 6, n = idx & 63;
        Xs[n * 132 + c] = x[((size_t)b * C + c) * NTOK + n0 + n];
    }
    __syncthreads();

    const int n  = tid & 63;
    const int og = tid >> 6;

    float acc[16];
#pragma unroll
    for (int j = 0; j < 16; j++) acc[j] = bias[og * 16 + j];
    for (int cc = 0; cc < 32; cc++) {
        float4 x4 = *(const float4*)&Xs[n * 132 + cc * 4];
#pragma unroll
        for (int j = 0; j < 16; j++) {
            float4 w4 = *(const float4*)&Ws[(og * 16 + j) * 128 + cc * 4];
            acc[j] += x4.x * w4.x; acc[j] += x4.y * w4.y;
            acc[j] += x4.z * w4.z; acc[j] += x4.w * w4.w;
        }
    }

    __align__(16) __half hb[16], lb[16];
#pragma unroll
    for (int j = 0; j < 16; j++) {
        float v = fmaxf(acc[j], 0.0f);
        __half h = __float2half_rn(v);
        hb[j] = h;
        lb[j] = __float2half_rn(v - __half2float(h));
    }
    size_t base = ((size_t)b * NTOK + n0 + n) * CH + og * 16;
    *(uint4*)&ohi[base]     = ((const uint4*)hb)[0];
    *(uint4*)&ohi[base + 8] = ((const uint4*)hb)[1];
    *(uint4*)&olo[base]     = ((const uint4*)lb)[0];
    *(uint4*)&olo[base + 8] = ((const uint4*)lb)[1];
}

// ---------------------------------------------------------------------------
// Gate projection (fp32, channel-major)
// ---------------------------------------------------------------------------
__global__ __launch_bounds__(256)
void proj_gate(const float* __restrict__ x, const float* __restrict__ W,
               const float* __restrict__ bias, float* __restrict__ out)
{
    extern __shared__ float smg[];
    float* Ws = smg;                 // 128*128
    float* Xs = smg + 128 * 128;     // 64*132

    const int b   = blockIdx.y;
    const int n0  = blockIdx.x * 64;
    const int tid = threadIdx.x;

    for (int idx = tid; idx < 128 * 128; idx += 256) Ws[idx] = W[idx];
    for (int idx = tid; idx < 128 * 64; idx += 256) {
        int c = idx >> 6, n = idx & 63;
        Xs[n * 132 + c] = x[((size_t)b * C + c) * NTOK + n0 + n];
    }
    __syncthreads();

    const int n  = tid & 63;
    const int og = tid >> 6;

    float acc[32];
#pragma unroll
    for (int j = 0; j < 32; j++) acc[j] = bias[og * 32 + j];
    for (int cc = 0; cc < 32; cc++) {
        float4 x4 = *(const float4*)&Xs[n * 132 + cc * 4];
#pragma unroll
        for (int j = 0; j < 32; j++) {
            float4 w4 = *(const float4*)&Ws[(og * 32 + j) * 128 + cc * 4];
            acc[j] += x4.x * w4.x; acc[j] += x4.y * w4.y;
            acc[j] += x4.z * w4.z; acc[j] += x4.w * w4.w;
        }
    }
#pragma unroll
    for (int j = 0; j < 32; j++)
        out[((size_t)b * C + og * 32 + j) * NTOK + n0 + n] = acc[j];
}

// ---------------------------------------------------------------------------
// Split V (= ref, native [b][c][n]) into fp16 hi/lo
// ---------------------------------------------------------------------------
__global__ __launch_bounds__(256)
void split_v(const float* __restrict__ ref,
             __half* __restrict__ vhi, __half* __restrict__ vlo)
{
    size_t i = ((size_t)blockIdx.x * 256 + threadIdx.x) * 8;
    float4 a = *(const float4*)(ref + i);
    float4 b = *(const float4*)(ref + i + 4);
    float v[8] = {a.x, a.y, a.z, a.w, b.x, b.y, b.z, b.w};
    __align__(16) __half h[8], l[8];
#pragma unroll
    for (int j = 0; j < 8; j++) {
        h[j] = __float2half_rn(v[j]);
        l[j] = __float2half_rn(v[j] - __half2float(h[j]));
    }
    *(uint4*)(vhi + i) = *(const uint4*)h;
    *(uint4*)(vlo + i) = *(const uint4*)l;
}

// ---------------------------------------------------------------------------
// mma.sync flash attention + gate, fp16 splits, cp.async double-buffered K/V.
//   QK: 3-term (Qhi.Khi + Qhi.Klo + Qlo.Khi), AV: 2-term (Phi.Vhi + Phi.Vlo)
// SMEM: 2 buffers x { KH[64][72] KL[64][72] VH[128][72] VL[128][72] } = 108KB
// ---------------------------------------------------------------------------
#define OFF_KH 0
#define OFF_KL 9216
#define OFF_VH 18432
#define OFF_VL 36864
#define BUF    55296
#define SMEM_ATTN (2 * BUF)
#define OFF_QH 0
#define OFF_QL 18432

__global__ __launch_bounds__(256, 1)
void attn_mma(const __half* __restrict__ Qhi, const __half* __restrict__ Qlo,
              const __half* __restrict__ Khi, const __half* __restrict__ Klo,
              const __half* __restrict__ Vhi, const __half* __restrict__ Vlo,
              const float* __restrict__ G, float* __restrict__ out)
{
    extern __shared__ __align__(16) char smc[];
    const uint32_t sb = smem_u32(smc);

    const int tid  = threadIdx.x;
    const int wid  = tid >> 5, lane = tid & 31;
    const int b    = blockIdx.y;
    const int n0   = blockIdx.x * TQ;
    const int rbase = wid * 16;

    // ---- stage Q (hi+lo) into buffer region, pull A-fragments to registers ----
    {
        const uint4* qh = (const uint4*)(Qhi + ((size_t)b * NTOK + n0) * CH);
        const uint4* ql = (const uint4*)(Qlo + ((size_t)b * NTOK + n0) * CH);
        for (int i = tid; i < 1024; i += 256) {       // 128 rows x 8 x 16B
            int r = i >> 3, j = i & 7;
            *(uint4*)(smc + OFF_QH + r * 144 + j * 16) = qh[i];
            *(uint4*)(smc + OFF_QL + r * 144 + j * 16) = ql[i];
        }
    }
    __syncthreads();

    uint32_t qa[4][4], qb[4][4];
    {
        const int ar = rbase + (lane & 15);
        const int ac = 8 * (lane >> 4);
#pragma unroll
        for (int kk = 0; kk < 4; kk++) {
            uint32_t off = (uint32_t)(ar * RS + kk * 16 + ac) * 2;
            ldsm4(qa[kk], sb + OFF_QH + off);
            ldsm4(qb[kk], sb + OFF_QL + off);
        }
    }
    __syncthreads();    // Q reads done before prefetch overwrites the region

    // ---- cp.async prefetch of K/V tile into buffer bsel ----
    const __half* KHb = Khi + (size_t)b * NTOK * CH;
    const __half* KLb = Klo + (size_t)b * NTOK * CH;
    const __half* VHb = Vhi + (size_t)b * C * NTOK;
    const __half* VLb = Vlo + (size_t)b * C * NTOK;
    auto prefetch = [&](int t, int bsel) {
        uint32_t base = sb + (uint32_t)bsel * BUF;
        const __half* khp = KHb + (size_t)t * TK * CH;
        const __half* klp = KLb + (size_t)t * TK * CH;
        for (int i = tid; i < 512; i += 256) {        // 64 rows x 8 x 16B
            int r = i >> 3, j = i & 7;
            uint32_t d = base + r * 144 + j * 16;
            cpa16(d + OFF_KH, khp + r * 64 + j * 8);
            cpa16(d + OFF_KL, klp + r * 64 + j * 8);
        }
        const __half* vhp = VHb + t * TK;
        const __half* vlp = VLb + t * TK;
        for (int i = tid; i < 1024; i += 256) {       // 128 rows x 8 x 16B
            int c = i >> 3, j = i & 7;
            uint32_t d = base + c * 144 + j * 16;
            cpa16(d + OFF_VH, vhp + (size_t)c * NTOK + j * 8);
            cpa16(d + OFF_VL, vlp + (size_t)c * NTOK + j * 8);
        }
    };

    float o[16][4];
#pragma unroll
    for (int jn = 0; jn < 16; jn++)
#pragma unroll
        for (int e = 0; e < 4; e++) o[jn][e] = 0.0f;
    float mx0 = -1e30f, mx1 = -1e30f, ls0 = 0.0f, ls1 = 0.0f;

    const int bn  = lane & 7;
    const int bk8 = 8 * ((lane >> 3) & 1);

    prefetch(0, 0);
    CP_COMMIT();

    for (int t = 0; t < KTILES; t++) {
        __syncthreads();                 // all warps done reading buf (t+1)&1
        if (t + 1 < KTILES) prefetch(t + 1, (t + 1) & 1);
        CP_COMMIT();
        CP_WAIT1();                      // tile-t group complete
        __syncthreads();                 // cross-warp visibility of tile t
        const uint32_t base = sb + (uint32_t)(t & 1) * BUF;

        // ---- S = Q.K^T, 3-term fp16 compensation ----
        float s[8][4];
#pragma unroll
        for (int j = 0; j < 8; j++)
#pragma unroll
            for (int e = 0; e < 4; e++) s[j][e] = 0.0f;

#pragma unroll
        for (int kk = 0; kk < 4; kk++) {
#pragma unroll
            for (int j = 0; j < 8; j++) {
                uint32_t kh2[2], kl2[2];
                uint32_t ka = base + OFF_KH +
                    (uint32_t)((j * 8 + bn) * RS + kk * 16 + bk8) * 2;
                ldsm2(kh2, ka);
                ldsm2(kl2, ka + (OFF_KL - OFF_KH));
                mma_f16(s[j], qa[kk], kh2);
                mma_f16(s[j], qa[kk], kl2);
                mma_f16(s[j], qb[kk], kh2);
            }
        }

        // ---- online softmax ----
        float a0 = -1e30f, a1 = -1e30f;
#pragma unroll
        for (int j = 0; j < 8; j++) {
            a0 = fmaxf(a0, fmaxf(s[j][0], s[j][1]));
            a1 = fmaxf(a1, fmaxf(s[j][2], s[j][3]));
        }
        a0 = fmaxf(a0, __shfl_xor_sync(0xffffffffu, a0, 1));
        a0 = fmaxf(a0, __shfl_xor_sync(0xffffffffu, a0, 2));
        a1 = fmaxf(a1, __shfl_xor_sync(0xffffffffu, a1, 1));
        a1 = fmaxf(a1, __shfl_xor_sync(0xffffffffu, a1, 2));
        float mn0 = fmaxf(mx0, a0), mn1 = fmaxf(mx1, a1);
        float cr0 = __expf(mx0 - mn0), cr1 = __expf(mx1 - mn1);
        float ps0 = 0.0f, ps1 = 0.0f;
#pragma unroll
        for (int j = 0; j < 8; j++) {
            s[j][0] = __expf(s[j][0] - mn0); ps0 += s[j][0];
            s[j][1] = __expf(s[j][1] - mn0); ps0 += s[j][1];
            s[j][2] = __expf(s[j][2] - mn1); ps1 += s[j][2];
            s[j][3] = __expf(s[j][3] - mn1); ps1 += s[j][3];
        }
        ps0 += __shfl_xor_sync(0xffffffffu, ps0, 1);
        ps0 += __shfl_xor_sync(0xffffffffu, ps0, 2);
        ps1 += __shfl_xor_sync(0xffffffffu, ps1, 1);
        ps1 += __shfl_xor_sync(0xffffffffu, ps1, 2);
        ls0 = ls0 * cr0 + ps0;  ls1 = ls1 * cr1 + ps1;
        mx0 = mn0;  mx1 = mn1;
#pragma unroll
        for (int jn = 0; jn < 16; jn++) {
            o[jn][0] *= cr0; o[jn][1] *= cr0;
            o[jn][2] *= cr1; o[jn][3] *= cr1;
        }

        // ---- P -> fp16 A-fragments (register remap, no residual) ----
        uint32_t ph[4][4];
#pragma unroll
        for (int kk = 0; kk < 4; kk++) {
            int j0 = 2 * kk, j1 = 2 * kk + 1;
            ph[kk][0] = cvt2h(s[j0][1], s[j0][0]);
            ph[kk][1] = cvt2h(s[j0][3], s[j0][2]);
            ph[kk][2] = cvt2h(s[j1][1], s[j1][0]);
            ph[kk][3] = cvt2h(s[j1][3], s[j1][2]);
        }

        // ---- O += P.V, 2-term (V hi+lo) ----
#pragma unroll
        for (int kk = 0; kk < 4; kk++) {
#pragma unroll
            for (int jn = 0; jn < 16; jn++) {
                uint32_t vh2[2], vl2[2];
                uint32_t va = base + OFF_VH +
                    (uint32_t)((jn * 8 + bn) * RS + kk * 16 + bk8) * 2;
                ldsm2(vh2, va);
                ldsm2(vl2, va + (OFF_VL - OFF_VH));
                mma_f16(o[jn], ph[kk], vh2);
                mma_f16(o[jn], ph[kk], vl2);
            }
        }
    }

    // ---- epilogue: normalize, gate, store ----
    const float inv0 = 1.0f / ls0, inv1 = 1.0f / ls1;
    const int tok = n0 + rbase + (lane >> 2);
#pragma unroll
    for (int jn = 0; jn < 16; jn++) {
        int c = jn * 8 + 2 * (lane & 3);
        size_t g = ((size_t)b * C + c) * NTOK + tok;
        out[g]            = o[jn][0] * inv0 * G[g];
        out[g + NTOK]     = o[jn][1] * inv0 * G[g + NTOK];
        out[g + 8]        = o[jn][2] * inv1 * G[g + 8];
        out[g + NTOK + 8] = o[jn][3] * inv1 * G[g + NTOK + 8];
    }
}

// ---------------------------------------------------------------------------
extern "C" void kernel_launch(void* const* d_in, const int* in_sizes, int n_in,
                              void* d_out, int out_size)
{
    const float* tgt   = (const float*)d_in[0];
    const float* refp  = (const float*)d_in[1];
    const float* W_tgt = (const float*)d_in[2];
    const float* b_tgt = (const float*)d_in[3];
    const float* W_ref = (const float*)d_in[4];
    const float* b_ref = (const float*)d_in[5];
    const float* W_out = (const float*)d_in[6];
    const float* b_out = (const float*)d_in[7];
    float* out = (float*)d_out;

    __half *qh, *ql, *kh, *kl, *vh, *vl; float* gp;
    cudaGetSymbolAddress((void**)&qh, g_Qhi);
    cudaGetSymbolAddress((void**)&ql, g_Qlo);
    cudaGetSymbolAddress((void**)&kh, g_Khi);
    cudaGetSymbolAddress((void**)&kl, g_Klo);
    cudaGetSymbolAddress((void**)&vh, g_Vhi);
    cudaGetSymbolAddress((void**)&vl, g_Vlo);
    cudaGetSymbolAddress((void**)&gp, g_G);

    const int smemQK = (64 * 128 + 64 * 132) * 4;
    const int smemG  = (128 * 128 + 64 * 132) * 4;

    cudaFuncSetAttribute(proj_qk,   cudaFuncAttributeMaxDynamicSharedMemorySize, smemQK);
    cudaFuncSetAttribute(proj_gate, cudaFuncAttributeMaxDynamicSharedMemorySize, smemG);
    cudaFuncSetAttribute(attn_mma,  cudaFuncAttributeMaxDynamicSharedMemorySize, SMEM_ATTN);

    dim3 pg(NTOK / 64, BS);
    proj_qk  <<<pg, 256, smemQK>>>(tgt,  W_tgt, b_tgt, qh, ql);
    proj_qk  <<<pg, 256, smemQK>>>(refp, W_ref, b_ref, kh, kl);
    proj_gate<<<pg, 256, smemG >>>(tgt,  W_out, b_out, gp);
    split_v<<<(BS * C * NTOK) / (256 * 8), 256>>>(refp, vh, vl);

    attn_mma<<<dim3(NTOK / TQ, BS), 256, SMEM_ATTN>>>(qh, ql, kh, kl, vh, vl, gp, out);
}

// round 7
// speedup vs baseline: 4.9497x; 1.4254x over previous
#include <cuda_runtime.h>
#include <cuda_fp16.h>
#include <math.h>
#include <stdint.h>

#define BS    8
#define C     128
#define CH    64
#define NTOK  4096
#define TQ    128
#define TK    64
#define KTILES (NTOK/TK)
#define RS    72        // smem row stride in fp16 elems (144B)

// ---------------------------------------------------------------------------
// Static scratch
// ---------------------------------------------------------------------------
__device__ __half g_Qhi[(size_t)BS * NTOK * CH];
__device__ __half g_Qlo[(size_t)BS * NTOK * CH];
__device__ __half g_Khi[(size_t)BS * NTOK * CH];
__device__ __half g_Klo[(size_t)BS * NTOK * CH];
__device__ __half g_Vhi[(size_t)BS * C * NTOK];   // [b][c][n]
__device__ __half g_Wh [C * C];                   // W_out hi  [co][ci]
__device__ __half g_Wl [C * C];                   // W_out lo

// ---------------------------------------------------------------------------
// PTX helpers (baseline ISA)
// ---------------------------------------------------------------------------
__device__ __forceinline__ uint32_t smem_u32(const void* p) {
    uint32_t a;
    asm("{ .reg .u64 t; cvta.to.shared.u64 t, %1; cvt.u32.u64 %0, t; }"
        : "=r"(a) : "l"(p));
    return a;
}
__device__ __forceinline__ void ldsm4(uint32_t* r, uint32_t a) {
    asm volatile("ldmatrix.sync.aligned.m8n8.x4.shared.b16 {%0,%1,%2,%3}, [%4];"
        : "=r"(r[0]), "=r"(r[1]), "=r"(r[2]), "=r"(r[3]) : "r"(a));
}
__device__ __forceinline__ void mma_f16(float* d, const uint32_t* a, const uint32_t* b) {
    asm volatile("mma.sync.aligned.m16n8k16.row.col.f32.f16.f16.f32 "
        "{%0,%1,%2,%3},{%4,%5,%6,%7},{%8,%9},{%0,%1,%2,%3};"
        : "+f"(d[0]), "+f"(d[1]), "+f"(d[2]), "+f"(d[3])
        : "r"(a[0]), "r"(a[1]), "r"(a[2]), "r"(a[3]), "r"(b[0]), "r"(b[1]));
}
__device__ __forceinline__ uint32_t cvt2h(float hi, float lo) {
    uint32_t r;
    asm("cvt.rn.f16x2.f32 %0, %1, %2;" : "=r"(r) : "f"(hi), "f"(lo));
    return r;
}
__device__ __forceinline__ uint32_t ex2h2(uint32_t x) {
    uint32_t r;
    asm("ex2.approx.f16x2 %0, %1;" : "=r"(r) : "r"(x));
    return r;
}
__device__ __forceinline__ void cpa16(uint32_t dst, const void* src) {
    asm volatile("cp.async.cg.shared.global [%0], [%1], 16;" :: "r"(dst), "l"(src));
}
#define CP_COMMIT() asm volatile("cp.async.commit_group;" ::: "memory")
#define CP_WAIT1()  asm volatile("cp.async.wait_group 1;" ::: "memory")
#define CP_WAIT0()  asm volatile("cp.async.wait_group 0;" ::: "memory")

// ---------------------------------------------------------------------------
// Projection for Q/K: relu(W.x + b), split to fp16 hi/lo, token-major
// ---------------------------------------------------------------------------
__global__ __launch_bounds__(256)
void proj_qk(const float* __restrict__ x, const float* __restrict__ W,
             const float* __restrict__ bias,
             __half* __restrict__ ohi, __half* __restrict__ olo)
{
    extern __shared__ float smf[];
    float* Ws = smf;                 // 64*128
    float* Xs = smf + 64 * 128;      // 64*132

    const int b   = blockIdx.y;
    const int n0  = blockIdx.x * 64;
    const int tid = threadIdx.x;

    for (int idx = tid; idx < 64 * 128; idx += 256) Ws[idx] = W[idx];
    for (int idx = tid; idx < 128 * 64; idx += 256) {
        int c = idx >> 6, n = idx & 63;
        Xs[n * 132 + c] = x[((size_t)b * C + c) * NTOK + n0 + n];
    }
    __syncthreads();

    const int n  = tid & 63;
    const int og = tid >> 6;

    float acc[16];
#pragma unroll
    for (int j = 0; j < 16; j++) acc[j] = bias[og * 16 + j];
    for (int cc = 0; cc < 32; cc++) {
        float4 x4 = *(const float4*)&Xs[n * 132 + cc * 4];
#pragma unroll
        for (int j = 0; j < 16; j++) {
            float4 w4 = *(const float4*)&Ws[(og * 16 + j) * 128 + cc * 4];
            acc[j] += x4.x * w4.x; acc[j] += x4.y * w4.y;
            acc[j] += x4.z * w4.z; acc[j] += x4.w * w4.w;
        }
    }

    __align__(16) __half hb[16], lb[16];
#pragma unroll
    for (int j = 0; j < 16; j++) {
        float v = fmaxf(acc[j], 0.0f);
        __half h = __float2half_rn(v);
        hb[j] = h;
        lb[j] = __float2half_rn(v - __half2float(h));
    }
    size_t base = ((size_t)b * NTOK + n0 + n) * CH + og * 16;
    *(uint4*)&ohi[base]     = ((const uint4*)hb)[0];
    *(uint4*)&ohi[base + 8] = ((const uint4*)hb)[1];
    *(uint4*)&olo[base]     = ((const uint4*)lb)[0];
    *(uint4*)&olo[base + 8] = ((const uint4*)lb)[1];
}

// ---------------------------------------------------------------------------
// Convert V (= ref, [b][c][n]) to fp16 (hi only)
// ---------------------------------------------------------------------------
__global__ __launch_bounds__(256)
void conv_v(const float* __restrict__ ref, __half* __restrict__ vhi)
{
    size_t i = ((size_t)blockIdx.x * 256 + threadIdx.x) * 8;
    float4 a = *(const float4*)(ref + i);
    float4 b = *(const float4*)(ref + i + 4);
    float v[8] = {a.x, a.y, a.z, a.w, b.x, b.y, b.z, b.w};
    __align__(16) __half h[8];
#pragma unroll
    for (int j = 0; j < 8; j++) h[j] = __float2half_rn(v[j]);
    *(uint4*)(vhi + i) = *(const uint4*)h;
}

// ---------------------------------------------------------------------------
// Split W_out (128x128 fp32) to fp16 hi/lo
// ---------------------------------------------------------------------------
__global__ __launch_bounds__(256)
void split_w(const float* __restrict__ W, __half* __restrict__ wh,
             __half* __restrict__ wl)
{
    int i = blockIdx.x * 256 + threadIdx.x;
    float x = W[i];
    __half h = __float2half_rn(x);
    wh[i] = h;
    wl[i] = __float2half_rn(x - __half2float(h));
}

// ---------------------------------------------------------------------------
// Flash attention + fused gate GEMM.
//   Loop: QK 3-term fp16, P via ex2.f16x2, row-sum via ones-MMA, AV 1-term V.
//   Epilogue: gate = W_out . tgt as fp16 3-term HMMA in freed SMEM.
// SMEM: 2 x { KH[64][72] KL[64][72] VH[128][72] } = 73728 B
// ---------------------------------------------------------------------------
#define OFF_KH 0
#define OFF_KL 9216
#define OFF_VH 18432
#define BUF    36864
#define SMEM_ATTN (2 * BUF)
#define OFF_QH 0
#define OFF_QL 36864
#define EP_WH  0
#define EP_WL  18432
#define EP_TH  36864
#define EP_TL  55296

__global__ __launch_bounds__(256, 1)
void attn_mma(const __half* __restrict__ Qhi, const __half* __restrict__ Qlo,
              const __half* __restrict__ Khi, const __half* __restrict__ Klo,
              const __half* __restrict__ Vhi,
              const __half* __restrict__ Wh,  const __half* __restrict__ Wl,
              const float* __restrict__ tgt,  const float* __restrict__ b_out,
              float* __restrict__ out)
{
    extern __shared__ __align__(16) char smc[];
    const uint32_t sb = smem_u32(smc);

    const int tid   = threadIdx.x;
    const int wid   = tid >> 5, lane = tid & 31;
    const int b     = blockIdx.y;
    const int n0    = blockIdx.x * TQ;
    const int rbase = wid * 16;
    const int lg    = lane >> 3;          // ldsm4 matrix group 0..3
    const int ln8   = lane & 7;
    const int lgr   = (lg >> 1) * 8 + ln8;      // row within 16-row pair
    const int lko   = 8 * (lg & 1);             // k-half select

    // ---- stage Q, pull A-fragments ----
    {
        const uint4* qh = (const uint4*)(Qhi + ((size_t)b * NTOK + n0) * CH);
        const uint4* ql = (const uint4*)(Qlo + ((size_t)b * NTOK + n0) * CH);
        for (int i = tid; i < 1024; i += 256) {
            int r = i >> 3, j = i & 7;
            *(uint4*)(smc + OFF_QH + r * 144 + j * 16) = qh[i];
            *(uint4*)(smc + OFF_QL + r * 144 + j * 16) = ql[i];
        }
    }
    __syncthreads();

    uint32_t qa[4][4], qb[4][4];
    {
        const int ar = rbase + (lane & 15);
        const int ac = 8 * (lane >> 4);
#pragma unroll
        for (int kk = 0; kk < 4; kk++) {
            uint32_t off = (uint32_t)(ar * RS + kk * 16 + ac) * 2;
            ldsm4(qa[kk], sb + OFF_QH + off);
            ldsm4(qb[kk], sb + OFF_QL + off);
        }
    }
    __syncthreads();

    const __half* KHb = Khi + (size_t)b * NTOK * CH;
    const __half* KLb = Klo + (size_t)b * NTOK * CH;
    const __half* VHb = Vhi + (size_t)b * C * NTOK;
    auto prefetch = [&](int t, int bsel) {
        uint32_t base = sb + (uint32_t)bsel * BUF;
        const __half* khp = KHb + (size_t)t * TK * CH;
        const __half* klp = KLb + (size_t)t * TK * CH;
        for (int i = tid; i < 512; i += 256) {
            int r = i >> 3, j = i & 7;
            uint32_t d = base + r * 144 + j * 16;
            cpa16(d + OFF_KH, khp + r * 64 + j * 8);
            cpa16(d + OFF_KL, klp + r * 64 + j * 8);
        }
        const __half* vhp = VHb + t * TK;
        for (int i = tid; i < 1024; i += 256) {
            int c = i >> 3, j = i & 7;
            cpa16(base + OFF_VH + c * 144 + j * 16, vhp + (size_t)c * NTOK + j * 8);
        }
    };

    float o[16][4];
#pragma unroll
    for (int jn = 0; jn < 16; jn++)
#pragma unroll
        for (int e = 0; e < 4; e++) o[jn][e] = 0.0f;
    float osum[4] = {0.f, 0.f, 0.f, 0.f};
    float mx0 = -1e30f, mx1 = -1e30f;

    const uint32_t ones2[2] = {0x3C003C00u, 0x3C003C00u};
    const float L2E = 1.4426950408889634f;

    prefetch(0, 0);
    CP_COMMIT();

    for (int t = 0; t < KTILES; t++) {
        __syncthreads();
        if (t + 1 < KTILES) prefetch(t + 1, (t + 1) & 1);
        CP_COMMIT();
        CP_WAIT1();
        __syncthreads();
        const uint32_t base = sb + (uint32_t)(t & 1) * BUF;

        // ---- S = Q.K^T, 3-term fp16 ----
        float s[8][4];
#pragma unroll
        for (int j = 0; j < 8; j++)
#pragma unroll
            for (int e = 0; e < 4; e++) s[j][e] = 0.0f;

#pragma unroll
        for (int kk = 0; kk < 4; kk++) {
#pragma unroll
            for (int jp = 0; jp < 4; jp++) {
                uint32_t kh4[4], kl4[4];
                uint32_t ka = base + OFF_KH +
                    (uint32_t)((jp * 16 + lgr) * RS + kk * 16 + lko) * 2;
                ldsm4(kh4, ka);
                ldsm4(kl4, ka + (OFF_KL - OFF_KH));
                mma_f16(s[2 * jp],     qa[kk], kh4);
                mma_f16(s[2 * jp + 1], qa[kk], kh4 + 2);
                mma_f16(s[2 * jp],     qa[kk], kl4);
                mma_f16(s[2 * jp + 1], qa[kk], kl4 + 2);
                mma_f16(s[2 * jp],     qb[kk], kh4);
                mma_f16(s[2 * jp + 1], qb[kk], kh4 + 2);
            }
        }

        // ---- online max + conditional rescale ----
        float a0 = -1e30f, a1 = -1e30f;
#pragma unroll
        for (int j = 0; j < 8; j++) {
            a0 = fmaxf(a0, fmaxf(s[j][0], s[j][1]));
            a1 = fmaxf(a1, fmaxf(s[j][2], s[j][3]));
        }
        a0 = fmaxf(a0, __shfl_xor_sync(0xffffffffu, a0, 1));
        a0 = fmaxf(a0, __shfl_xor_sync(0xffffffffu, a0, 2));
        a1 = fmaxf(a1, __shfl_xor_sync(0xffffffffu, a1, 1));
        a1 = fmaxf(a1, __shfl_xor_sync(0xffffffffu, a1, 2));
        float mn0 = fmaxf(mx0, a0), mn1 = fmaxf(mx1, a1);
        if (__any_sync(0xffffffffu, (mn0 > mx0) || (mn1 > mx1))) {
            float cr0 = __expf(mx0 - mn0), cr1 = __expf(mx1 - mn1);
#pragma unroll
            for (int jn = 0; jn < 16; jn++) {
                o[jn][0] *= cr0; o[jn][1] *= cr0;
                o[jn][2] *= cr1; o[jn][3] *= cr1;
            }
            osum[0] *= cr0; osum[1] *= cr0;
            osum[2] *= cr1; osum[3] *= cr1;
        }
        mx0 = mn0; mx1 = mn1;

        // ---- P = 2^((s-m)*L2E) via ex2.f16x2, packed as A-fragments ----
        const float mL0 = mn0 * L2E, mL1 = mn1 * L2E;
        uint32_t ph[4][4];
#pragma unroll
        for (int kk = 0; kk < 4; kk++) {
            int j0 = 2 * kk, j1 = 2 * kk + 1;
            ph[kk][0] = ex2h2(cvt2h(fmaf(s[j0][1], L2E, -mL0),
                                    fmaf(s[j0][0], L2E, -mL0)));
            ph[kk][1] = ex2h2(cvt2h(fmaf(s[j0][3], L2E, -mL1),
                                    fmaf(s[j0][2], L2E, -mL1)));
            ph[kk][2] = ex2h2(cvt2h(fmaf(s[j1][1], L2E, -mL0),
                                    fmaf(s[j1][0], L2E, -mL0)));
            ph[kk][3] = ex2h2(cvt2h(fmaf(s[j1][3], L2E, -mL1),
                                    fmaf(s[j1][2], L2E, -mL1)));
        }

        // ---- O += P.V (single V term) and row-sum via ones-MMA ----
#pragma unroll
        for (int kk = 0; kk < 4; kk++) {
            mma_f16(osum, ph[kk], ones2);
#pragma unroll
            for (int jp = 0; jp < 8; jp++) {
                uint32_t vh4[4];
                uint32_t va = base + OFF_VH +
                    (uint32_t)((jp * 16 + lgr) * RS + kk * 16 + lko) * 2;
                ldsm4(vh4, va);
                mma_f16(o[2 * jp],     ph[kk], vh4);
                mma_f16(o[2 * jp + 1], ph[kk], vh4 + 2);
            }
        }
    }

    // ================= epilogue: fused gate GEMM =================
    CP_WAIT0();
    __syncthreads();

    float g[16][4];
#pragma unroll
    for (int jn = 0; jn < 16; jn++) {
        float ba = b_out[jn * 8 + 2 * (lane & 3)];
        float bb = b_out[jn * 8 + 2 * (lane & 3) + 1];
        g[jn][0] = ba; g[jn][1] = bb; g[jn][2] = ba; g[jn][3] = bb;
    }

    const float* tb = tgt + (size_t)b * C * NTOK + n0;
#pragma unroll 1
    for (int half = 0; half < 2; half++) {
        // stage W_out half [co][64]
        const __half* whp = Wh + half * 64;
        const __half* wlp = Wl + half * 64;
        for (int i = tid; i < 1024; i += 256) {
            int r = i >> 3, j = i & 7;
            *(uint4*)(smc + EP_WH + r * 144 + j * 16) = *(const uint4*)(whp + r * 128 + j * 8);
            *(uint4*)(smc + EP_WL + r * 144 + j * 16) = *(const uint4*)(wlp + r * 128 + j * 8);
        }
        // stage tgt half transposed+split: [tok][c]
        for (int i = 0; i < 16; i++) {
            int tok = lane + 32 * (i & 3);
            int cp  = (tid >> 5) + 8 * (i >> 2);
            int c   = half * 64 + cp * 2;
            float x0 = tb[(size_t)c * NTOK + tok];
            float x1 = tb[(size_t)(c + 1) * NTOK + tok];
            __half h0 = __float2half_rn(x0), h1 = __float2half_rn(x1);
            __half l0 = __float2half_rn(x0 - __half2float(h0));
            __half l1 = __float2half_rn(x1 - __half2float(h1));
            *(__half2*)(smc + EP_TH + tok * 144 + cp * 4) = __halves2half2(h0, h1);
            *(__half2*)(smc + EP_TL + tok * 144 + cp * 4) = __halves2half2(l0, l1);
        }
        __syncthreads();

        uint32_t ah[4][4], al[4][4];
        {
            const int ar = rbase + (lane & 15);
            const int ac = 8 * (lane >> 4);
#pragma unroll
            for (int kk = 0; kk < 4; kk++) {
                uint32_t off = (uint32_t)(ar * RS + kk * 16 + ac) * 2;
                ldsm4(ah[kk], sb + EP_TH + off);
                ldsm4(al[kk], sb + EP_TL + off);
            }
        }
#pragma unroll
        for (int jn = 0; jn < 16; jn++) {
            uint32_t bh01[4], bh23[4], bl01[4], bl23[4];
            uint32_t wa = sb + EP_WH + (uint32_t)((jn * 8 + ln8) * RS + lg * 8) * 2;
            ldsm4(bh01, wa);
            ldsm4(bh23, wa + 64);
            ldsm4(bl01, wa + (EP_WL - EP_WH));
            ldsm4(bl23, wa + (EP_WL - EP_WH) + 64);
            mma_f16(g[jn], ah[0], bh01);  mma_f16(g[jn], ah[1], bh01 + 2);
            mma_f16(g[jn], ah[2], bh23);  mma_f16(g[jn], ah[3], bh23 + 2);
            mma_f16(g[jn], ah[0], bl01);  mma_f16(g[jn], ah[1], bl01 + 2);
            mma_f16(g[jn], ah[2], bl23);  mma_f16(g[jn], ah[3], bl23 + 2);
            mma_f16(g[jn], al[0], bh01);  mma_f16(g[jn], al[1], bh01 + 2);
            mma_f16(g[jn], al[2], bh23);  mma_f16(g[jn], al[3], bh23 + 2);
        }
        __syncthreads();
    }

    // ---- normalize, gate, store ----
    const float inv0 = 1.0f / osum[0], inv1 = 1.0f / osum[2];
    const int tok = n0 + rbase + (lane >> 2);
#pragma unroll
    for (int jn = 0; jn < 16; jn++) {
        int c = jn * 8 + 2 * (lane & 3);
        size_t gi = ((size_t)b * C + c) * NTOK + tok;
        out[gi]            = o[jn][0] * inv0 * g[jn][0];
        out[gi + NTOK]     = o[jn][1] * inv0 * g[jn][1];
        out[gi + 8]        = o[jn][2] * inv1 * g[jn][2];
        out[gi + NTOK + 8] = o[jn][3] * inv1 * g[jn][3];
    }
}

// ---------------------------------------------------------------------------
extern "C" void kernel_launch(void* const* d_in, const int* in_sizes, int n_in,
                              void* d_out, int out_size)
{
    const float* tgt   = (const float*)d_in[0];
    const float* refp  = (const float*)d_in[1];
    const float* W_tgt = (const float*)d_in[2];
    const float* b_tgt = (const float*)d_in[3];
    const float* W_ref = (const float*)d_in[4];
    const float* b_ref = (const float*)d_in[5];
    const float* W_out = (const float*)d_in[6];
    const float* b_out = (const float*)d_in[7];
    float* out = (float*)d_out;

    __half *qh, *ql, *kh, *kl, *vh, *wh, *wl;
    cudaGetSymbolAddress((void**)&qh, g_Qhi);
    cudaGetSymbolAddress((void**)&ql, g_Qlo);
    cudaGetSymbolAddress((void**)&kh, g_Khi);
    cudaGetSymbolAddress((void**)&kl, g_Klo);
    cudaGetSymbolAddress((void**)&vh, g_Vhi);
    cudaGetSymbolAddress((void**)&wh, g_Wh);
    cudaGetSymbolAddress((void**)&wl, g_Wl);

    const int smemQK = (64 * 128 + 64 * 132) * 4;

    cudaFuncSetAttribute(proj_qk,  cudaFuncAttributeMaxDynamicSharedMemorySize, smemQK);
    cudaFuncSetAttribute(attn_mma, cudaFuncAttributeMaxDynamicSharedMemorySize, SMEM_ATTN);

    dim3 pg(NTOK / 64, BS);
    proj_qk<<<pg, 256, smemQK>>>(tgt,  W_tgt, b_tgt, qh, ql);
    proj_qk<<<pg, 256, smemQK>>>(refp, W_ref, b_ref, kh, kl);
    conv_v<<<(BS * C * NTOK) / (256 * 8), 256>>>(refp, vh);
    split_w<<<(C * C) / 256, 256>>>(W_out, wh, wl);

    attn_mma<<<dim3(NTOK / TQ, BS), 256, SMEM_ATTN>>>(
        qh, ql, kh, kl, vh, wh, wl, tgt, b_out, out);
}

// round 8
// speedup vs baseline: 5.5789x; 1.1271x over previous
#include <cuda_runtime.h>
#include <cuda_fp16.h>
#include <math.h>
#include <stdint.h>

#define BS    8
#define C     128
#define CH    64
#define NTOK  4096
#define TQ    128
#define TK    64
#define KTILES (NTOK/TK)
#define RS    72        // smem row stride in fp16 elems (144B)

// ---------------------------------------------------------------------------
// Static scratch
// ---------------------------------------------------------------------------
__device__ __half g_Khi[(size_t)BS * NTOK * CH];  // [b][n][d]
__device__ __half g_Klo[(size_t)BS * NTOK * CH];
__device__ __half g_Vhi[(size_t)BS * C * NTOK];   // [b][c][n]
__device__ __half g_Wh [C * C];                   // W_out hi  [co][ci]
__device__ __half g_Wl [C * C];
__device__ __half g_WtH[CH * C];                  // W_tgt hi  [co][ci]
__device__ __half g_WtL[CH * C];
__device__ __half g_WrH[CH * C];                  // W_ref hi
__device__ __half g_WrL[CH * C];

// ---------------------------------------------------------------------------
// PTX helpers (baseline ISA)
// ---------------------------------------------------------------------------
__device__ __forceinline__ uint32_t smem_u32(const void* p) {
    uint32_t a;
    asm("{ .reg .u64 t; cvta.to.shared.u64 t, %1; cvt.u32.u64 %0, t; }"
        : "=r"(a) : "l"(p));
    return a;
}
__device__ __forceinline__ void ldsm4(uint32_t* r, uint32_t a) {
    asm volatile("ldmatrix.sync.aligned.m8n8.x4.shared.b16 {%0,%1,%2,%3}, [%4];"
        : "=r"(r[0]), "=r"(r[1]), "=r"(r[2]), "=r"(r[3]) : "r"(a));
}
__device__ __forceinline__ void mma_f16(float* d, const uint32_t* a, const uint32_t* b) {
    asm volatile("mma.sync.aligned.m16n8k16.row.col.f32.f16.f16.f32 "
        "{%0,%1,%2,%3},{%4,%5,%6,%7},{%8,%9},{%0,%1,%2,%3};"
        : "+f"(d[0]), "+f"(d[1]), "+f"(d[2]), "+f"(d[3])
        : "r"(a[0]), "r"(a[1]), "r"(a[2]), "r"(a[3]), "r"(b[0]), "r"(b[1]));
}
__device__ __forceinline__ uint32_t cvt2h(float hi, float lo) {
    uint32_t r;
    asm("cvt.rn.f16x2.f32 %0, %1, %2;" : "=r"(r) : "f"(hi), "f"(lo));
    return r;
}
__device__ __forceinline__ uint32_t ex2h2(uint32_t x) {
    uint32_t r;
    asm("ex2.approx.f16x2 %0, %1;" : "=r"(r) : "r"(x));
    return r;
}
__device__ __forceinline__ void cpa16(uint32_t dst, const void* src) {
    asm volatile("cp.async.cg.shared.global [%0], [%1], 16;" :: "r"(dst), "l"(src));
}
#define CP_COMMIT() asm volatile("cp.async.commit_group;" ::: "memory")
#define CP_WAIT1()  asm volatile("cp.async.wait_group 1;" ::: "memory")
#define CP_WAIT0()  asm volatile("cp.async.wait_group 0;" ::: "memory")

// ---------------------------------------------------------------------------
// Generic fp32 -> fp16 hi/lo split
// ---------------------------------------------------------------------------
__global__ __launch_bounds__(256)
void split_gen(const float* __restrict__ W, __half* __restrict__ h,
               __half* __restrict__ l)
{
    int i = blockIdx.x * 256 + threadIdx.x;
    float x = W[i];
    __half hh = __float2half_rn(x);
    h[i] = hh;
    l[i] = __float2half_rn(x - __half2float(hh));
}

// ---------------------------------------------------------------------------
// Convert V (= ref, [b][c][n]) to fp16
// ---------------------------------------------------------------------------
__global__ __launch_bounds__(256)
void conv_v(const float* __restrict__ ref, __half* __restrict__ vhi)
{
    size_t i = ((size_t)blockIdx.x * 256 + threadIdx.x) * 8;
    float4 a = *(const float4*)(ref + i);
    float4 b = *(const float4*)(ref + i + 4);
    float v[8] = {a.x, a.y, a.z, a.w, b.x, b.y, b.z, b.w};
    __align__(16) __half h[8];
#pragma unroll
    for (int j = 0; j < 8; j++) h[j] = __float2half_rn(v[j]);
    *(uint4*)(vhi + i) = *(const uint4*)h;
}

// ---------------------------------------------------------------------------
// Shared projection core: acc[8][4] += 3-term HMMA of (x half-tile) . (W half)
// Stages one 64-channel half of x (transposed+split) and W, runs 96 MMAs/warp.
// smem layout: WH[64][72], WL[64][72], TH[128][72], TL[128][72]
// ---------------------------------------------------------------------------
#define PR_WH 0
#define PR_WL 9216
#define PR_TH 18432
#define PR_TL 36864
#define PR_SZ 55296

template<typename SM>
__device__ __forceinline__ void proj_half(
    SM* smc, uint32_t sb, int half,
    const float* __restrict__ xb,            // x + b*C*NTOK + n0  ([c][n])
    const __half* __restrict__ WH, const __half* __restrict__ WL,  // [64][128]
    int tid, int wid, int lane, int rbase, float acc[8][4])
{
    const int lg  = lane >> 3, ln8 = lane & 7;
    const __half* whp = WH + half * 64;
    const __half* wlp = WL + half * 64;
    for (int i = tid; i < 512; i += 256) {
        int r = i >> 3, j = i & 7;
        *(uint4*)((char*)smc + PR_WH + r * 144 + j * 16) = *(const uint4*)(whp + r * 128 + j * 8);
        *(uint4*)((char*)smc + PR_WL + r * 144 + j * 16) = *(const uint4*)(wlp + r * 128 + j * 8);
    }
#pragma unroll
    for (int i = 0; i < 16; i++) {
        int tok = lane + 32 * (i & 3);
        int cp  = wid + 8 * (i >> 2);
        int c   = half * 64 + cp * 2;
        float x0 = xb[(size_t)c * NTOK + tok];
        float x1 = xb[(size_t)(c + 1) * NTOK + tok];
        __half h0 = __float2half_rn(x0), h1 = __float2half_rn(x1);
        __half l0 = __float2half_rn(x0 - __half2float(h0));
        __half l1 = __float2half_rn(x1 - __half2float(h1));
        *(__half2*)((char*)smc + PR_TH + tok * 144 + cp * 4) = __halves2half2(h0, h1);
        *(__half2*)((char*)smc + PR_TL + tok * 144 + cp * 4) = __halves2half2(l0, l1);
    }
    __syncthreads();

    uint32_t ah[4][4], al[4][4];
    {
        const int ar = rbase + (lane & 15);
        const int ac = 8 * (lane >> 4);
#pragma unroll
        for (int kk = 0; kk < 4; kk++) {
            uint32_t off = (uint32_t)(ar * RS + kk * 16 + ac) * 2;
            ldsm4(ah[kk], sb + PR_TH + off);
            ldsm4(al[kk], sb + PR_TL + off);
        }
    }
#pragma unroll
    for (int jn = 0; jn < 8; jn++) {
        uint32_t bh01[4], bh23[4], bl01[4], bl23[4];
        uint32_t wa = sb + PR_WH + (uint32_t)((jn * 8 + ln8) * RS + lg * 8) * 2;
        ldsm4(bh01, wa);
        ldsm4(bh23, wa + 64);
        ldsm4(bl01, wa + (PR_WL - PR_WH));
        ldsm4(bl23, wa + (PR_WL - PR_WH) + 64);
        mma_f16(acc[jn], ah[0], bh01);  mma_f16(acc[jn], ah[1], bh01 + 2);
        mma_f16(acc[jn], ah[2], bh23);  mma_f16(acc[jn], ah[3], bh23 + 2);
        mma_f16(acc[jn], ah[0], bl01);  mma_f16(acc[jn], ah[1], bl01 + 2);
        mma_f16(acc[jn], ah[2], bl23);  mma_f16(acc[jn], ah[3], bl23 + 2);
        mma_f16(acc[jn], al[0], bh01);  mma_f16(acc[jn], al[1], bh01 + 2);
        mma_f16(acc[jn], al[2], bh23);  mma_f16(acc[jn], al[3], bh23 + 2);
    }
    __syncthreads();
}

// ---------------------------------------------------------------------------
// K projection (tensor-core): K = relu(W_ref . ref + b_ref), split hi/lo,
// stored token-major [b][n][64]
// ---------------------------------------------------------------------------
__global__ __launch_bounds__(256)
void proj_k_tc(const float* __restrict__ ref,
               const __half* __restrict__ WrH, const __half* __restrict__ WrL,
               const float* __restrict__ b_ref,
               __half* __restrict__ khi, __half* __restrict__ klo)
{
    extern __shared__ __align__(16) char smk[];
    const uint32_t sb = smem_u32(smk);
    const int tid = threadIdx.x, wid = tid >> 5, lane = tid & 31;
    const int b = blockIdx.y, n0 = blockIdx.x * 128;
    const int rbase = wid * 16;
    const int col0 = 2 * (lane & 3);

    float acc[8][4];
#pragma unroll
    for (int jn = 0; jn < 8; jn++) {
        float2 bb = *(const float2*)&b_ref[jn * 8 + col0];
        acc[jn][0] = bb.x; acc[jn][1] = bb.y;
        acc[jn][2] = bb.x; acc[jn][3] = bb.y;
    }
    const float* xb = ref + (size_t)b * C * NTOK + n0;
#pragma unroll 1
    for (int half = 0; half < 2; half++)
        proj_half(smk, sb, half, xb, WrH, WrL, tid, wid, lane, rbase, acc);

    const int r0 = rbase + (lane >> 2);
#pragma unroll
    for (int jn = 0; jn < 8; jn++) {
        int col = jn * 8 + col0;
        float v0 = fmaxf(acc[jn][0], 0.f), v1 = fmaxf(acc[jn][1], 0.f);
        float v2 = fmaxf(acc[jn][2], 0.f), v3 = fmaxf(acc[jn][3], 0.f);
        __half h0 = __float2half_rn(v0), h1 = __float2half_rn(v1);
        __half h2 = __float2half_rn(v2), h3 = __float2half_rn(v3);
        size_t i0 = ((size_t)b * NTOK + n0 + r0) * CH + col;
        size_t i1 = ((size_t)b * NTOK + n0 + r0 + 8) * CH + col;
        *(__half2*)&khi[i0] = __halves2half2(h0, h1);
        *(__half2*)&khi[i1] = __halves2half2(h2, h3);
        *(__half2*)&klo[i0] = __halves2half2(__float2half_rn(v0 - __half2float(h0)),
                                             __float2half_rn(v1 - __half2float(h1)));
        *(__half2*)&klo[i1] = __halves2half2(__float2half_rn(v2 - __half2float(h2)),
                                             __float2half_rn(v3 - __half2float(h3)));
    }
}

// ---------------------------------------------------------------------------
// Flash attention with fused Q projection and fused gate GEMM.
// SMEM: 2 x { KH[64][72] KL[64][72] VH[128][72] } = 73728 B
// ---------------------------------------------------------------------------
#define OFF_KH 0
#define OFF_KL 9216
#define OFF_VH 18432
#define BUF    36864
#define SMEM_ATTN (2 * BUF)
#define EP_WH  0
#define EP_WL  18432
#define EP_TH  36864
#define EP_TL  55296

__global__ __launch_bounds__(256, 1)
void attn_mma(const __half* __restrict__ WtH, const __half* __restrict__ WtL,
              const float* __restrict__ b_tgt,
              const __half* __restrict__ Khi, const __half* __restrict__ Klo,
              const __half* __restrict__ Vhi,
              const __half* __restrict__ Wh,  const __half* __restrict__ Wl,
              const float* __restrict__ tgt,  const float* __restrict__ b_out,
              float* __restrict__ out)
{
    extern __shared__ __align__(16) char smc[];
    const uint32_t sb = smem_u32(smc);

    const int tid   = threadIdx.x;
    const int wid   = tid >> 5, lane = tid & 31;
    const int b     = blockIdx.y;
    const int n0    = blockIdx.x * TQ;
    const int rbase = wid * 16;
    const int lg    = lane >> 3;
    const int ln8   = lane & 7;
    const int lgr   = (lg >> 1) * 8 + ln8;
    const int lko   = 8 * (lg & 1);
    const int col0  = 2 * (lane & 3);

    const float* tb = tgt + (size_t)b * C * NTOK + n0;

    // ======== fused Q projection: Q = relu(W_tgt . tgt_tile + b_tgt) ========
    uint32_t qa[4][4], qb[4][4];
    {
        float qacc[8][4];
#pragma unroll
        for (int jn = 0; jn < 8; jn++) {
            float2 bb = *(const float2*)&b_tgt[jn * 8 + col0];
            qacc[jn][0] = bb.x; qacc[jn][1] = bb.y;
            qacc[jn][2] = bb.x; qacc[jn][3] = bb.y;
        }
#pragma unroll 1
        for (int half = 0; half < 2; half++)
            proj_half(smc, sb, half, tb, WtH, WtL, tid, wid, lane, rbase, qacc);

        // relu + split C-fragments directly into Q A-fragments
#pragma unroll
        for (int kk = 0; kk < 4; kk++) {
#pragma unroll
            for (int hh = 0; hh < 2; hh++) {
                int j = 2 * kk + hh;
                float v0 = fmaxf(qacc[j][0], 0.f), v1 = fmaxf(qacc[j][1], 0.f);
                float v2 = fmaxf(qacc[j][2], 0.f), v3 = fmaxf(qacc[j][3], 0.f);
                uint32_t h01 = cvt2h(v1, v0), h23 = cvt2h(v3, v2);
                float2 f01 = __half22float2(*(__half2*)&h01);
                float2 f23 = __half22float2(*(__half2*)&h23);
                qa[kk][2 * hh]     = h01;
                qa[kk][2 * hh + 1] = h23;
                qb[kk][2 * hh]     = cvt2h(v1 - f01.y, v0 - f01.x);
                qb[kk][2 * hh + 1] = cvt2h(v3 - f23.y, v2 - f23.x);
            }
        }
    }

    // ======== main flash-attention loop ========
    const __half* KHb = Khi + (size_t)b * NTOK * CH;
    const __half* KLb = Klo + (size_t)b * NTOK * CH;
    const __half* VHb = Vhi + (size_t)b * C * NTOK;
    auto prefetch = [&](int t, int bsel) {
        uint32_t base = sb + (uint32_t)bsel * BUF;
        const __half* khp = KHb + (size_t)t * TK * CH;
        const __half* klp = KLb + (size_t)t * TK * CH;
        for (int i = tid; i < 512; i += 256) {
            int r = i >> 3, j = i & 7;
            uint32_t d = base + r * 144 + j * 16;
            cpa16(d + OFF_KH, khp + r * 64 + j * 8);
            cpa16(d + OFF_KL, klp + r * 64 + j * 8);
        }
        const __half* vhp = VHb + t * TK;
        for (int i = tid; i < 1024; i += 256) {
            int c = i >> 3, j = i & 7;
            cpa16(base + OFF_VH + c * 144 + j * 16, vhp + (size_t)c * NTOK + j * 8);
        }
    };

    float o[16][4];
#pragma unroll
    for (int jn = 0; jn < 16; jn++)
#pragma unroll
        for (int e = 0; e < 4; e++) o[jn][e] = 0.0f;
    float osum[4] = {0.f, 0.f, 0.f, 0.f};
    float mx0 = -1e30f, mx1 = -1e30f;

    const uint32_t ones2[2] = {0x3C003C00u, 0x3C003C00u};
    const float L2E = 1.4426950408889634f;

    prefetch(0, 0);
    CP_COMMIT();

    for (int t = 0; t < KTILES; t++) {
        __syncthreads();
        if (t + 1 < KTILES) prefetch(t + 1, (t + 1) & 1);
        CP_COMMIT();
        CP_WAIT1();
        __syncthreads();
        const uint32_t base = sb + (uint32_t)(t & 1) * BUF;

        float s[8][4];
#pragma unroll
        for (int j = 0; j < 8; j++)
#pragma unroll
            for (int e = 0; e < 4; e++) s[j][e] = 0.0f;

#pragma unroll
        for (int kk = 0; kk < 4; kk++) {
#pragma unroll
            for (int jp = 0; jp < 4; jp++) {
                uint32_t kh4[4], kl4[4];
                uint32_t ka = base + OFF_KH +
                    (uint32_t)((jp * 16 + lgr) * RS + kk * 16 + lko) * 2;
                ldsm4(kh4, ka);
                ldsm4(kl4, ka + (OFF_KL - OFF_KH));
                mma_f16(s[2 * jp],     qa[kk], kh4);
                mma_f16(s[2 * jp + 1], qa[kk], kh4 + 2);
                mma_f16(s[2 * jp],     qa[kk], kl4);
                mma_f16(s[2 * jp + 1], qa[kk], kl4 + 2);
                mma_f16(s[2 * jp],     qb[kk], kh4);
                mma_f16(s[2 * jp + 1], qb[kk], kh4 + 2);
            }
        }

        float a0 = -1e30f, a1 = -1e30f;
#pragma unroll
        for (int j = 0; j < 8; j++) {
            a0 = fmaxf(a0, fmaxf(s[j][0], s[j][1]));
            a1 = fmaxf(a1, fmaxf(s[j][2], s[j][3]));
        }
        a0 = fmaxf(a0, __shfl_xor_sync(0xffffffffu, a0, 1));
        a0 = fmaxf(a0, __shfl_xor_sync(0xffffffffu, a0, 2));
        a1 = fmaxf(a1, __shfl_xor_sync(0xffffffffu, a1, 1));
        a1 = fmaxf(a1, __shfl_xor_sync(0xffffffffu, a1, 2));
        float mn0 = fmaxf(mx0, a0), mn1 = fmaxf(mx1, a1);
        if (__any_sync(0xffffffffu, (mn0 > mx0) || (mn1 > mx1))) {
            float cr0 = __expf(mx0 - mn0), cr1 = __expf(mx1 - mn1);
#pragma unroll
            for (int jn = 0; jn < 16; jn++) {
                o[jn][0] *= cr0; o[jn][1] *= cr0;
                o[jn][2] *= cr1; o[jn][3] *= cr1;
            }
            osum[0] *= cr0; osum[1] *= cr0;
            osum[2] *= cr1; osum[3] *= cr1;
        }
        mx0 = mn0; mx1 = mn1;

        const float mL0 = mn0 * L2E, mL1 = mn1 * L2E;
        uint32_t ph[4][4];
#pragma unroll
        for (int kk = 0; kk < 4; kk++) {
            int j0 = 2 * kk, j1 = 2 * kk + 1;
            ph[kk][0] = ex2h2(cvt2h(fmaf(s[j0][1], L2E, -mL0),
                                    fmaf(s[j0][0], L2E, -mL0)));
            ph[kk][1] = ex2h2(cvt2h(fmaf(s[j0][3], L2E, -mL1),
                                    fmaf(s[j0][2], L2E, -mL1)));
            ph[kk][2] = ex2h2(cvt2h(fmaf(s[j1][1], L2E, -mL0),
                                    fmaf(s[j1][0], L2E, -mL0)));
            ph[kk][3] = ex2h2(cvt2h(fmaf(s[j1][3], L2E, -mL1),
                                    fmaf(s[j1][2], L2E, -mL1)));
        }

#pragma unroll
        for (int kk = 0; kk < 4; kk++) {
            mma_f16(osum, ph[kk], ones2);
#pragma unroll
            for (int jp = 0; jp < 8; jp++) {
                uint32_t vh4[4];
                uint32_t va = base + OFF_VH +
                    (uint32_t)((jp * 16 + lgr) * RS + kk * 16 + lko) * 2;
                ldsm4(vh4, va);
                mma_f16(o[2 * jp],     ph[kk], vh4);
                mma_f16(o[2 * jp + 1], ph[kk], vh4 + 2);
            }
        }
    }

    // ======== epilogue: fused gate GEMM ========
    CP_WAIT0();
    __syncthreads();

    float g[16][4];
#pragma unroll
    for (int jn = 0; jn < 16; jn++) {
        float ba = b_out[jn * 8 + col0];
        float bb = b_out[jn * 8 + col0 + 1];
        g[jn][0] = ba; g[jn][1] = bb; g[jn][2] = ba; g[jn][3] = bb;
    }

#pragma unroll 1
    for (int half = 0; half < 2; half++) {
        const __half* whp = Wh + half * 64;
        const __half* wlp = Wl + half * 64;
        for (int i = tid; i < 1024; i += 256) {
            int r = i >> 3, j = i & 7;
            *(uint4*)(smc + EP_WH + r * 144 + j * 16) = *(const uint4*)(whp + r * 128 + j * 8);
            *(uint4*)(smc + EP_WL + r * 144 + j * 16) = *(const uint4*)(wlp + r * 128 + j * 8);
        }
        for (int i = 0; i < 16; i++) {
            int tok = lane + 32 * (i & 3);
            int cp  = wid + 8 * (i >> 2);
            int c   = half * 64 + cp * 2;
            float x0 = tb[(size_t)c * NTOK + tok];
            float x1 = tb[(size_t)(c + 1) * NTOK + tok];
            __half h0 = __float2half_rn(x0), h1 = __float2half_rn(x1);
            __half l0 = __float2half_rn(x0 - __half2float(h0));
            __half l1 = __float2half_rn(x1 - __half2float(h1));
            *(__half2*)(smc + EP_TH + tok * 144 + cp * 4) = __halves2half2(h0, h1);
            *(__half2*)(smc + EP_TL + tok * 144 + cp * 4) = __halves2half2(l0, l1);
        }
        __syncthreads();

        uint32_t ah[4][4], al[4][4];
        {
            const int ar = rbase + (lane & 15);
            const int ac = 8 * (lane >> 4);
#pragma unroll
            for (int kk = 0; kk < 4; kk++) {
                uint32_t off = (uint32_t)(ar * RS + kk * 16 + ac) * 2;
                ldsm4(ah[kk], sb + EP_TH + off);
                ldsm4(al[kk], sb + EP_TL + off);
            }
        }
#pragma unroll
        for (int jn = 0; jn < 16; jn++) {
            uint32_t bh01[4], bh23[4], bl01[4], bl23[4];
            uint32_t wa = sb + EP_WH + (uint32_t)((jn * 8 + ln8) * RS + lg * 8) * 2;
            ldsm4(bh01, wa);
            ldsm4(bh23, wa + 64);
            ldsm4(bl01, wa + (EP_WL - EP_WH));
            ldsm4(bl23, wa + (EP_WL - EP_WH) + 64);
            mma_f16(g[jn], ah[0], bh01);  mma_f16(g[jn], ah[1], bh01 + 2);
            mma_f16(g[jn], ah[2], bh23);  mma_f16(g[jn], ah[3], bh23 + 2);
            mma_f16(g[jn], ah[0], bl01);  mma_f16(g[jn], ah[1], bl01 + 2);
            mma_f16(g[jn], ah[2], bl23);  mma_f16(g[jn], ah[3], bl23 + 2);
            mma_f16(g[jn], al[0], bh01);  mma_f16(g[jn], al[1], bh01 + 2);
            mma_f16(g[jn], al[2], bh23);  mma_f16(g[jn], al[3], bh23 + 2);
        }
        __syncthreads();
    }

    // ---- normalize, gate, store ----
    const float inv0 = 1.0f / osum[0], inv1 = 1.0f / osum[2];
    const int tok = n0 + rbase + (lane >> 2);
#pragma unroll
    for (int jn = 0; jn < 16; jn++) {
        int c = jn * 8 + col0;
        size_t gi = ((size_t)b * C + c) * NTOK + tok;
        out[gi]            = o[jn][0] * inv0 * g[jn][0];
        out[gi + NTOK]     = o[jn][1] * inv0 * g[jn][1];
        out[gi + 8]        = o[jn][2] * inv1 * g[jn][2];
        out[gi + NTOK + 8] = o[jn][3] * inv1 * g[jn][3];
    }
}

// ---------------------------------------------------------------------------
extern "C" void kernel_launch(void* const* d_in, const int* in_sizes, int n_in,
                              void* d_out, int out_size)
{
    const float* tgt   = (const float*)d_in[0];
    const float* refp  = (const float*)d_in[1];
    const float* W_tgt = (const float*)d_in[2];
    const float* b_tgt = (const float*)d_in[3];
    const float* W_ref = (const float*)d_in[4];
    const float* b_ref = (const float*)d_in[5];
    const float* W_out = (const float*)d_in[6];
    const float* b_out = (const float*)d_in[7];
    float* out = (float*)d_out;

    __half *kh, *kl, *vh, *wh, *wl, *wth, *wtl, *wrh, *wrl;
    cudaGetSymbolAddress((void**)&kh,  g_Khi);
    cudaGetSymbolAddress((void**)&kl,  g_Klo);
    cudaGetSymbolAddress((void**)&vh,  g_Vhi);
    cudaGetSymbolAddress((void**)&wh,  g_Wh);
    cudaGetSymbolAddress((void**)&wl,  g_Wl);
    cudaGetSymbolAddress((void**)&wth, g_WtH);
    cudaGetSymbolAddress((void**)&wtl, g_WtL);
    cudaGetSymbolAddress((void**)&wrh, g_WrH);
    cudaGetSymbolAddress((void**)&wrl, g_WrL);

    cudaFuncSetAttribute(proj_k_tc, cudaFuncAttributeMaxDynamicSharedMemorySize, PR_SZ);
    cudaFuncSetAttribute(attn_mma,  cudaFuncAttributeMaxDynamicSharedMemorySize, SMEM_ATTN);

    split_gen<<<(CH * C) / 256, 256>>>(W_tgt, wth, wtl);
    split_gen<<<(CH * C) / 256, 256>>>(W_ref, wrh, wrl);
    split_gen<<<(C * C) / 256, 256>>>(W_out, wh, wl);
    conv_v<<<(BS * C * NTOK) / (256 * 8), 256>>>(refp, vh);
    proj_k_tc<<<dim3(NTOK / 128, BS), 256, PR_SZ>>>(refp, wrh, wrl, b_ref, kh, kl);

    attn_mma<<<dim3(NTOK / TQ, BS), 256, SMEM_ATTN>>>(
        wth, wtl, b_tgt, kh, kl, vh, wh, wl, tgt, b_out, out);
}